// round 2
// baseline (speedup 1.0000x reference)
#include <cuda_runtime.h>
#include <math.h>

#define N_NODES 100000
#define E_EDGES 1600000
#define DIM 128

// ---- scratch (device globals: allocation-free) ----
__device__ float g_h  [N_NODES * DIM];   // 51.2 MB  h = x@W_pre + b
__device__ float g_agg[N_NODES * DIM];   // 51.2 MB  sum_e norm_e * h[row_e]
__device__ float g_msg[N_NODES * DIM];   // 51.2 MB  sum_e ew_e   * h[row_e]
__device__ float g_deg[N_NODES];         // weighted in-degree
__device__ float g_cnt[N_NODES];         // edge count per target

// ---------------------------------------------------------------------------
// vector RED: 16B atomic add
// ---------------------------------------------------------------------------
__device__ __forceinline__ void red_add_v4(float* p, float x, float y, float z, float w) {
    asm volatile("red.global.add.v4.f32 [%0], {%1, %2, %3, %4};"
                 :: "l"(p), "f"(x), "f"(y), "f"(z), "f"(w) : "memory");
}

// ---------------------------------------------------------------------------
// K1: h = x @ W_pre + b    (64 rows/block, 256 thr; smem 96KB)
// ---------------------------------------------------------------------------
__global__ __launch_bounds__(256) void gemm_pre(
    const float* __restrict__ A, const float* __restrict__ W,
    const float* __restrict__ bias, float* __restrict__ C)
{
    extern __shared__ float smem[];
    float* Ws = smem;             // [128][128]
    float* As = smem + DIM * DIM; // [64][128]
    const int tid = threadIdx.x;
    const int row0 = blockIdx.x * 64;

    for (int i = tid; i < DIM * DIM / 4; i += 256)
        ((float4*)Ws)[i] = ((const float4*)W)[i];
    for (int i = tid; i < 64 * 32; i += 256) {
        int r = i >> 5, gr = row0 + r;
        ((float4*)As)[i] = (gr < N_NODES) ? ((const float4*)A)[gr * 32 + (i & 31)]
                                          : make_float4(0.f, 0.f, 0.f, 0.f);
    }
    __syncthreads();

    const int tc = tid & 31;   // 4-col group
    const int tr = tid >> 5;   // 8-row group
    float acc[8][4];
    #pragma unroll
    for (int i = 0; i < 8; ++i)
        acc[i][0] = acc[i][1] = acc[i][2] = acc[i][3] = 0.f;

    #pragma unroll 4
    for (int k = 0; k < DIM; ++k) {
        float4 w = ((const float4*)Ws)[k * 32 + tc];
        #pragma unroll
        for (int i = 0; i < 8; ++i) {
            float a = As[(tr * 8 + i) * DIM + k];
            acc[i][0] += a * w.x; acc[i][1] += a * w.y;
            acc[i][2] += a * w.z; acc[i][3] += a * w.w;
        }
    }
    float4 bb = ((const float4*)bias)[tc];
    #pragma unroll
    for (int i = 0; i < 8; ++i) {
        int gr = row0 + tr * 8 + i;
        if (gr < N_NODES) {
            float4 v = make_float4(acc[i][0] + bb.x, acc[i][1] + bb.y,
                                   acc[i][2] + bb.z, acc[i][3] + bb.w);
            ((float4*)C)[gr * 32 + tc] = v;
        }
    }
}

// ---------------------------------------------------------------------------
// K2: deg[c] += ew ; cnt[c] += 1
// ---------------------------------------------------------------------------
__global__ void deg_kernel(const int* __restrict__ ei,
                           const float* __restrict__ ew)
{
    int i = blockIdx.x * blockDim.x + threadIdx.x;
    int stride = gridDim.x * blockDim.x;
    for (; i < E_EDGES; i += stride) {
        int c = ei[E_EDGES + i];
        atomicAdd(&g_deg[c], ew[i]);
        atomicAdd(&g_cnt[c], 1.0f);
    }
}

// ---------------------------------------------------------------------------
// K3: one pass over edges; warp per edge.
//   agg[col] += norm * h[row] ;  msg[col] += ew * h[row]
// ---------------------------------------------------------------------------
__global__ __launch_bounds__(256) void edge_kernel(
    const int* __restrict__ ei, const float* __restrict__ ew)
{
    const int warp  = (blockIdx.x * blockDim.x + threadIdx.x) >> 5;
    const int lane  = threadIdx.x & 31;
    const int nwarp = (gridDim.x * blockDim.x) >> 5;
    for (int e = warp; e < E_EDGES; e += nwarp) {
        int r = ei[e];
        int c = ei[E_EDGES + e];
        float w  = ew[e];
        float dr = g_deg[r], dc = g_deg[c];
        float norm = (dr > 0.f && dc > 0.f) ? rsqrtf(dr) * w * rsqrtf(dc) : 0.f;

        float4 h = ((const float4*)g_h)[r * 32 + lane];
        float* pa = g_agg + (c * DIM + lane * 4);
        float* pm = g_msg + (c * DIM + lane * 4);
        red_add_v4(pa, norm * h.x, norm * h.y, norm * h.z, norm * h.w);
        red_add_v4(pm, w * h.x, w * h.y, w * h.z, w * h.w);
    }
}

// ---------------------------------------------------------------------------
// K4/K5: fused dual-GEMM + activation epilogue.
//   MODE 0 (ARMA): out[:, 0:128]   = relu(A1@W1 + A2@W2 + b)
//   MODE 1 (SAGE): A1 rows scaled by 1/max(cnt,1); elu(leaky(s))
// smem 192KB
// ---------------------------------------------------------------------------
template <int MODE>
__global__ __launch_bounds__(256) void gemm_dual(
    const float* __restrict__ A1, const float* __restrict__ W1,
    const float* __restrict__ A2, const float* __restrict__ W2,
    const float* __restrict__ bias, float* __restrict__ out)
{
    extern __shared__ float smem[];
    float* Ws1 = smem;
    float* Ws2 = smem + DIM * DIM;
    float* As1 = smem + 2 * DIM * DIM;
    float* As2 = As1 + 64 * DIM;
    const int tid  = threadIdx.x;
    const int row0 = blockIdx.x * 64;

    for (int i = tid; i < DIM * DIM / 4; i += 256) {
        ((float4*)Ws1)[i] = ((const float4*)W1)[i];
        ((float4*)Ws2)[i] = ((const float4*)W2)[i];
    }
    for (int i = tid; i < 64 * 32; i += 256) {
        int r = i >> 5, gr = row0 + r;
        float4 v1 = make_float4(0.f, 0.f, 0.f, 0.f), v2 = v1;
        if (gr < N_NODES) {
            v1 = ((const float4*)A1)[gr * 32 + (i & 31)];
            v2 = ((const float4*)A2)[gr * 32 + (i & 31)];
            if (MODE == 1) {
                float rc = 1.f / fmaxf(g_cnt[gr], 1.f);
                v1.x *= rc; v1.y *= rc; v1.z *= rc; v1.w *= rc;
            }
        }
        ((float4*)As1)[i] = v1;
        ((float4*)As2)[i] = v2;
    }
    __syncthreads();

    const int tc = tid & 31;
    const int tr = tid >> 5;
    float acc[8][4];
    #pragma unroll
    for (int i = 0; i < 8; ++i)
        acc[i][0] = acc[i][1] = acc[i][2] = acc[i][3] = 0.f;

    #pragma unroll 2
    for (int k = 0; k < DIM; ++k) {
        float4 w1 = ((const float4*)Ws1)[k * 32 + tc];
        float4 w2 = ((const float4*)Ws2)[k * 32 + tc];
        #pragma unroll
        for (int i = 0; i < 8; ++i) {
            float a1 = As1[(tr * 8 + i) * DIM + k];
            float a2 = As2[(tr * 8 + i) * DIM + k];
            acc[i][0] += a1 * w1.x; acc[i][1] += a1 * w1.y;
            acc[i][2] += a1 * w1.z; acc[i][3] += a1 * w1.w;
            acc[i][0] += a2 * w2.x; acc[i][1] += a2 * w2.y;
            acc[i][2] += a2 * w2.z; acc[i][3] += a2 * w2.w;
        }
    }

    float4 bb = ((const float4*)bias)[tc];
    #pragma unroll
    for (int i = 0; i < 8; ++i) {
        int gr = row0 + tr * 8 + i;
        if (gr >= N_NODES) continue;
        float v[4] = { acc[i][0] + bb.x, acc[i][1] + bb.y,
                       acc[i][2] + bb.z, acc[i][3] + bb.w };
        float4 o;
        if (MODE == 0) {
            o = make_float4(fmaxf(v[0], 0.f), fmaxf(v[1], 0.f),
                            fmaxf(v[2], 0.f), fmaxf(v[3], 0.f));
            ((float4*)out)[gr * 64 + tc] = o;              // cols [0,128)
        } else {
            o.x = v[0] > 0.f ? v[0] : expm1f(0.01f * v[0]);
            o.y = v[1] > 0.f ? v[1] : expm1f(0.01f * v[1]);
            o.z = v[2] > 0.f ? v[2] : expm1f(0.01f * v[2]);
            o.w = v[3] > 0.f ? v[3] : expm1f(0.01f * v[3]);
            ((float4*)out)[gr * 64 + 32 + tc] = o;         // cols [128,256)
        }
    }
}

// ---------------------------------------------------------------------------
extern "C" void kernel_launch(void* const* d_in, const int* in_sizes, int n_in,
                              void* d_out, int out_size)
{
    const float* x    = (const float*)d_in[0];
    const int*   ei   = (const int*)d_in[1];    // int32! (JAX x64 disabled)
    const float* ew   = (const float*)d_in[2];
    const float* Wpre = (const float*)d_in[3];
    const float* bpre = (const float*)d_in[4];
    const float* Wi   = (const float*)d_in[5];   // arma_init_w
    const float* Wr   = (const float*)d_in[6];   // arma_root_w
    const float* ba   = (const float*)d_in[7];   // arma_b
    const float* Wl   = (const float*)d_in[8];   // sage_l_w
    const float* bl   = (const float*)d_in[9];   // sage_l_b
    const float* Wr2  = (const float*)d_in[10];  // sage_r_w
    float* out = (float*)d_out;

    void *p_h, *p_agg, *p_msg, *p_deg, *p_cnt;
    cudaGetSymbolAddress(&p_h,   g_h);
    cudaGetSymbolAddress(&p_agg, g_agg);
    cudaGetSymbolAddress(&p_msg, g_msg);
    cudaGetSymbolAddress(&p_deg, g_deg);
    cudaGetSymbolAddress(&p_cnt, g_cnt);

    const int SMEM_PRE  = (DIM * DIM + 64 * DIM) * 4;          // 96 KB
    const int SMEM_DUAL = (2 * DIM * DIM + 2 * 64 * DIM) * 4;  // 192 KB
    cudaFuncSetAttribute(gemm_pre,     cudaFuncAttributeMaxDynamicSharedMemorySize, SMEM_PRE);
    cudaFuncSetAttribute(gemm_dual<0>, cudaFuncAttributeMaxDynamicSharedMemorySize, SMEM_DUAL);
    cudaFuncSetAttribute(gemm_dual<1>, cudaFuncAttributeMaxDynamicSharedMemorySize, SMEM_DUAL);

    cudaMemsetAsync(p_agg, 0, sizeof(float) * N_NODES * DIM);
    cudaMemsetAsync(p_msg, 0, sizeof(float) * N_NODES * DIM);
    cudaMemsetAsync(p_deg, 0, sizeof(float) * N_NODES);
    cudaMemsetAsync(p_cnt, 0, sizeof(float) * N_NODES);

    const int nblk = (N_NODES + 63) / 64;  // 1563

    gemm_pre<<<nblk, 256, SMEM_PRE>>>(x, Wpre, bpre, (float*)p_h);
    deg_kernel<<<1024, 256>>>(ei, ew);
    edge_kernel<<<2048, 256>>>(ei, ew);
    gemm_dual<0><<<nblk, 256, SMEM_DUAL>>>((const float*)p_agg, Wi,
                                           (const float*)p_h,   Wr, ba, out);
    gemm_dual<1><<<nblk, 256, SMEM_DUAL>>>((const float*)p_msg, Wl,
                                           (const float*)p_h,   Wr2, bl, out);
}

// round 4
// speedup vs baseline: 1.7698x; 1.7698x over previous
#include <cuda_runtime.h>
#include <stdint.h>
#include <math.h>

#define N_NODES 100000
#define E_EDGES 1600000
#define DIM 128

// ---- scratch (device globals: allocation-free) ----
__device__ float g_h  [N_NODES * DIM];   // h = x@W_pre + b
__device__ float g_agg[N_NODES * DIM];   // sum_e norm_e * h[row_e]
__device__ float g_msg[N_NODES * DIM];   // sum_e ew_e   * h[row_e]
__device__ float g_deg[N_NODES];
__device__ float g_cnt[N_NODES];
// transposed + tf32-rounded weights [out][in]
__device__ float g_wt_pre[DIM * DIM];
__device__ float g_wt_i  [DIM * DIM];
__device__ float g_wt_r  [DIM * DIM];
__device__ float g_wt_l  [DIM * DIM];
__device__ float g_wt_r2 [DIM * DIM];

__device__ __forceinline__ float to_tf32(float x) {
    unsigned int u;
    asm("cvt.rna.tf32.f32 %0, %1;" : "=r"(u) : "f"(x));
    return __uint_as_float(u);
}

__device__ __forceinline__ void red_add_v4(float* p, float x, float y, float z, float w) {
    asm volatile("red.global.add.v4.f32 [%0], {%1, %2, %3, %4};"
                 :: "l"(p), "f"(x), "f"(y), "f"(z), "f"(w) : "memory");
}

__device__ __forceinline__ void mma_tf32(float* c, float a0, float a1, float a2, float a3,
                                         float b0, float b1) {
    asm volatile(
        "mma.sync.aligned.m16n8k8.row.col.f32.tf32.tf32.f32 "
        "{%0,%1,%2,%3}, {%4,%5,%6,%7}, {%8,%9}, {%0,%1,%2,%3};"
        : "+f"(c[0]), "+f"(c[1]), "+f"(c[2]), "+f"(c[3])
        : "r"(__float_as_uint(a0)), "r"(__float_as_uint(a1)),
          "r"(__float_as_uint(a2)), "r"(__float_as_uint(a3)),
          "r"(__float_as_uint(b0)), "r"(__float_as_uint(b1)));
}

// ---------------------------------------------------------------------------
// K0: transpose all 5 weights [in][out] -> [out][in], tf32-rounded.
// grid (4,4,5), block (32,8)
// ---------------------------------------------------------------------------
__global__ void transpose_weights(const float* __restrict__ W0, const float* __restrict__ W1,
                                  const float* __restrict__ W2, const float* __restrict__ W3,
                                  const float* __restrict__ W4)
{
    __shared__ float t[32][33];
    const float* src; float* dst;
    switch (blockIdx.z) {
        case 0: src = W0; dst = g_wt_pre; break;
        case 1: src = W1; dst = g_wt_i;   break;
        case 2: src = W2; dst = g_wt_r;   break;
        case 3: src = W3; dst = g_wt_l;   break;
        default: src = W4; dst = g_wt_r2; break;
    }
    int x = blockIdx.x * 32 + threadIdx.x;         // out-dim col
    int y0 = blockIdx.y * 32;                      // in-dim row base
    for (int i = threadIdx.y; i < 32; i += 8)
        t[i][threadIdx.x] = src[(y0 + i) * DIM + x];
    __syncthreads();
    int xo = blockIdx.y * 32 + threadIdx.x;        // in-dim -> dst col
    int yo0 = blockIdx.x * 32;                     // out-dim -> dst row base
    for (int i = threadIdx.y; i < 32; i += 8)
        dst[(yo0 + i) * DIM + xo] = to_tf32(t[threadIdx.x][i]);
}

// ---------------------------------------------------------------------------
// Tensor-core GEMM: C[M=100000][128] = A_cat[M][KTOT] @ W_cat[KTOT][128] + b
//  KTOT=128: single matrix (MODE 2, out = g_h, stride 128)
//  KTOT=256: A_cat = [A1 | A2], W_cat^T = [WT1 ; WT2]
//   MODE 0 (ARMA): relu epilogue, out cols [0,128) of 256-stride out
//   MODE 1 (SAGE): A1 rows scaled by 1/max(cnt,1); elu(leaky) epi, cols [128,256)
// Block: 128x128 tile, 256 thr (8 warps 4Mx2N), K chunks of 64. smem 68KB.
// ---------------------------------------------------------------------------
template <int KTOT, int MODE>
__global__ __launch_bounds__(256, 2) void gemm_tc(
    const float* __restrict__ A1, const float* __restrict__ WT1,
    const float* __restrict__ A2, const float* __restrict__ WT2,
    const float* __restrict__ bias, float* __restrict__ out)
{
    extern __shared__ float smem[];
    float* As = smem;              // [128][68]
    float* Ws = smem + 128 * 68;   // [128][68]  (W^T rows = out-dim)

    const int tid  = threadIdx.x;
    const int row0 = blockIdx.x * 128;
    const int wid  = tid >> 5;
    const int lane = tid & 31;
    const int gid  = lane >> 2;
    const int tig  = lane & 3;
    const int warpM = (wid >> 1) * 32;
    const int warpN = (wid & 1) * 64;

    float acc[2][8][4];
    #pragma unroll
    for (int mt = 0; mt < 2; ++mt)
        #pragma unroll
        for (int nt = 0; nt < 8; ++nt)
            acc[mt][nt][0] = acc[mt][nt][1] = acc[mt][nt][2] = acc[mt][nt][3] = 0.f;

    for (int kc = 0; kc < KTOT; kc += 64) {
        const float* srcA = (KTOT == 256 && kc >= 128) ? A2 : A1;
        const float* srcW = (KTOT == 256 && kc >= 128) ? WT2 : WT1;
        const int koff4 = (kc & 127) >> 2;

        // stage A chunk: 128 rows x 16 float4
        #pragma unroll
        for (int it = 0; it < 8; ++it) {
            int idx = tid + it * 256;
            int r = idx >> 4, j = idx & 15;
            int gr = row0 + r;
            float4 v = make_float4(0.f, 0.f, 0.f, 0.f);
            if (gr < N_NODES) {
                v = ((const float4*)srcA)[gr * 32 + koff4 + j];
                if (MODE == 1 && kc < 128) {
                    float rc = 1.f / fmaxf(g_cnt[gr], 1.f);
                    v.x *= rc; v.y *= rc; v.z *= rc; v.w *= rc;
                }
            }
            v.x = to_tf32(v.x); v.y = to_tf32(v.y);
            v.z = to_tf32(v.z); v.w = to_tf32(v.w);
            *(float4*)&As[r * 68 + j * 4] = v;
        }
        // stage W^T chunk: 128 rows (out-dim) x 16 float4 (pre-converted tf32)
        #pragma unroll
        for (int it = 0; it < 8; ++it) {
            int idx = tid + it * 256;
            int n = idx >> 4, j = idx & 15;
            *(float4*)&Ws[n * 68 + j * 4] = ((const float4*)srcW)[n * 32 + koff4 + j];
        }
        __syncthreads();

        #pragma unroll
        for (int k8 = 0; k8 < 64; k8 += 8) {
            float a[2][4];
            #pragma unroll
            for (int mt = 0; mt < 2; ++mt) {
                int rb = warpM + mt * 16 + gid;
                a[mt][0] = As[rb * 68 + k8 + tig];
                a[mt][1] = As[(rb + 8) * 68 + k8 + tig];
                a[mt][2] = As[rb * 68 + k8 + tig + 4];
                a[mt][3] = As[(rb + 8) * 68 + k8 + tig + 4];
            }
            #pragma unroll
            for (int nt = 0; nt < 8; ++nt) {
                int nb = warpN + nt * 8 + gid;
                float b0 = Ws[nb * 68 + k8 + tig];
                float b1 = Ws[nb * 68 + k8 + tig + 4];
                mma_tf32(acc[0][nt], a[0][0], a[0][1], a[0][2], a[0][3], b0, b1);
                mma_tf32(acc[1][nt], a[1][0], a[1][1], a[1][2], a[1][3], b0, b1);
            }
        }
        __syncthreads();
    }

    // epilogue
    #pragma unroll
    for (int mt = 0; mt < 2; ++mt) {
        #pragma unroll
        for (int nt = 0; nt < 8; ++nt) {
            int col = warpN + nt * 8 + 2 * tig;
            float2 bb = *(const float2*)&bias[col];
            #pragma unroll
            for (int half = 0; half < 2; ++half) {
                int gr = row0 + warpM + mt * 16 + gid + half * 8;
                if (gr >= N_NODES) continue;
                float v0 = acc[mt][nt][half * 2 + 0] + bb.x;
                float v1 = acc[mt][nt][half * 2 + 1] + bb.y;
                float2 o;
                if (MODE == 0) {
                    o.x = fmaxf(v0, 0.f); o.y = fmaxf(v1, 0.f);
                    *(float2*)&out[gr * 256 + col] = o;
                } else if (MODE == 1) {
                    o.x = v0 > 0.f ? v0 : expm1f(0.01f * v0);
                    o.y = v1 > 0.f ? v1 : expm1f(0.01f * v1);
                    *(float2*)&out[gr * 256 + 128 + col] = o;
                } else {
                    o.x = v0; o.y = v1;
                    *(float2*)&out[gr * 128 + col] = o;
                }
            }
        }
    }
}

// ---------------------------------------------------------------------------
// deg[c] += ew ; cnt[c] += 1
// ---------------------------------------------------------------------------
__global__ void deg_kernel(const int* __restrict__ ei, const float* __restrict__ ew)
{
    int i = blockIdx.x * blockDim.x + threadIdx.x;
    int stride = gridDim.x * blockDim.x;
    for (; i < E_EDGES; i += stride) {
        int c = ei[E_EDGES + i];
        atomicAdd(&g_deg[c], ew[i]);
        atomicAdd(&g_cnt[c], 1.0f);
    }
}

// ---------------------------------------------------------------------------
// edge pass: warp per edge; agg[c] += norm*h[r]; msg[c] += w*h[r]
// ---------------------------------------------------------------------------
__global__ __launch_bounds__(256) void edge_kernel(
    const int* __restrict__ ei, const float* __restrict__ ew)
{
    const int warp  = (blockIdx.x * blockDim.x + threadIdx.x) >> 5;
    const int lane  = threadIdx.x & 31;
    const int nwarp = (gridDim.x * blockDim.x) >> 5;
    for (int e = warp; e < E_EDGES; e += nwarp) {
        int r = ei[e];
        int c = ei[E_EDGES + e];
        float w  = ew[e];
        float dr = g_deg[r], dc = g_deg[c];
        float norm = (dr > 0.f && dc > 0.f) ? rsqrtf(dr) * w * rsqrtf(dc) : 0.f;

        float4 h = ((const float4*)g_h)[r * 32 + lane];
        float* pa = g_agg + (c * DIM + lane * 4);
        float* pm = g_msg + (c * DIM + lane * 4);
        red_add_v4(pa, norm * h.x, norm * h.y, norm * h.z, norm * h.w);
        red_add_v4(pm, w * h.x, w * h.y, w * h.z, w * h.w);
    }
}

// ---------------------------------------------------------------------------
extern "C" void kernel_launch(void* const* d_in, const int* in_sizes, int n_in,
                              void* d_out, int out_size)
{
    const float* x    = (const float*)d_in[0];
    const int*   ei   = (const int*)d_in[1];    // int32 (JAX x64 disabled)
    const float* ew   = (const float*)d_in[2];
    const float* Wpre = (const float*)d_in[3];
    const float* bpre = (const float*)d_in[4];
    const float* Wi   = (const float*)d_in[5];
    const float* Wr   = (const float*)d_in[6];
    const float* ba   = (const float*)d_in[7];
    const float* Wl   = (const float*)d_in[8];
    const float* bl   = (const float*)d_in[9];
    const float* Wr2  = (const float*)d_in[10];
    float* out = (float*)d_out;

    void *p_h, *p_agg, *p_msg, *p_deg, *p_cnt;
    void *p_wtpre, *p_wti, *p_wtr, *p_wtl, *p_wtr2;
    cudaGetSymbolAddress(&p_h,   g_h);
    cudaGetSymbolAddress(&p_agg, g_agg);
    cudaGetSymbolAddress(&p_msg, g_msg);
    cudaGetSymbolAddress(&p_deg, g_deg);
    cudaGetSymbolAddress(&p_cnt, g_cnt);
    cudaGetSymbolAddress(&p_wtpre, g_wt_pre);
    cudaGetSymbolAddress(&p_wti,   g_wt_i);
    cudaGetSymbolAddress(&p_wtr,   g_wt_r);
    cudaGetSymbolAddress(&p_wtl,   g_wt_l);
    cudaGetSymbolAddress(&p_wtr2,  g_wt_r2);

    const int SMEM_TC = 2 * 128 * 68 * 4;  // 69,632 B
    cudaFuncSetAttribute(gemm_tc<128,2>, cudaFuncAttributeMaxDynamicSharedMemorySize, SMEM_TC);
    cudaFuncSetAttribute(gemm_tc<256,0>, cudaFuncAttributeMaxDynamicSharedMemorySize, SMEM_TC);
    cudaFuncSetAttribute(gemm_tc<256,1>, cudaFuncAttributeMaxDynamicSharedMemorySize, SMEM_TC);

    cudaMemsetAsync(p_agg, 0, sizeof(float) * N_NODES * DIM);
    cudaMemsetAsync(p_msg, 0, sizeof(float) * N_NODES * DIM);
    cudaMemsetAsync(p_deg, 0, sizeof(float) * N_NODES);
    cudaMemsetAsync(p_cnt, 0, sizeof(float) * N_NODES);

    transpose_weights<<<dim3(4,4,5), dim3(32,8)>>>(Wpre, Wi, Wr, Wl, Wr2);

    const int nblk = (N_NODES + 127) / 128;  // 782

    gemm_tc<128,2><<<nblk, 256, SMEM_TC>>>(x, (const float*)p_wtpre,
                                           nullptr, nullptr, bpre, (float*)p_h);
    deg_kernel<<<1024, 256>>>(ei, ew);
    edge_kernel<<<2048, 256>>>(ei, ew);
    gemm_tc<256,0><<<nblk, 256, SMEM_TC>>>((const float*)p_agg, (const float*)p_wti,
                                           (const float*)p_h,   (const float*)p_wtr,
                                           ba, out);
    gemm_tc<256,1><<<nblk, 256, SMEM_TC>>>((const float*)p_msg, (const float*)p_wtl,
                                           (const float*)p_h,   (const float*)p_wtr2,
                                           bl, out);
}

// round 5
// speedup vs baseline: 2.1777x; 1.2305x over previous
#include <cuda_runtime.h>
#include <stdint.h>
#include <math.h>

#define N_NODES 100000
#define E_EDGES 1600000
#define DIM 128

// ---- scratch (device globals: allocation-free) ----
__device__ float g_h  [N_NODES * DIM];   // h = x@W_pre + b
__device__ float g_agg[N_NODES * DIM];   // sum_e norm_e * h[src_e]
__device__ float g_msg[N_NODES * DIM];   // mean_e w_e * h[src_e]
__device__ float g_deg[N_NODES];         // weighted in-degree
__device__ int   g_hist[N_NODES];        // in-edge counts
__device__ int   g_rowptr[N_NODES + 1];  // CSR row pointer (by target)
__device__ int   g_wptr[N_NODES];        // write cursors for permute
__device__ int   g_srow[E_EDGES];        // CSR: source node per edge
__device__ float2 g_snw[E_EDGES];        // CSR: (norm, weight) per edge
// transposed + tf32-rounded weights [out][in]
__device__ float g_wt_pre[DIM * DIM];
__device__ float g_wt_i  [DIM * DIM];
__device__ float g_wt_r  [DIM * DIM];
__device__ float g_wt_l  [DIM * DIM];
__device__ float g_wt_r2 [DIM * DIM];

__device__ __forceinline__ float to_tf32(float x) {
    unsigned int u;
    asm("cvt.rna.tf32.f32 %0, %1;" : "=r"(u) : "f"(x));
    return __uint_as_float(u);
}

__device__ __forceinline__ void mma_tf32(float* c, float a0, float a1, float a2, float a3,
                                         float b0, float b1) {
    asm volatile(
        "mma.sync.aligned.m16n8k8.row.col.f32.tf32.tf32.f32 "
        "{%0,%1,%2,%3}, {%4,%5,%6,%7}, {%8,%9}, {%0,%1,%2,%3};"
        : "+f"(c[0]), "+f"(c[1]), "+f"(c[2]), "+f"(c[3])
        : "r"(__float_as_uint(a0)), "r"(__float_as_uint(a1)),
          "r"(__float_as_uint(a2)), "r"(__float_as_uint(a3)),
          "r"(__float_as_uint(b0)), "r"(__float_as_uint(b1)));
}

// ---------------------------------------------------------------------------
// transpose all 5 weights [in][out] -> [out][in], tf32-rounded
// ---------------------------------------------------------------------------
__global__ void transpose_weights(const float* __restrict__ W0, const float* __restrict__ W1,
                                  const float* __restrict__ W2, const float* __restrict__ W3,
                                  const float* __restrict__ W4)
{
    __shared__ float t[32][33];
    const float* src; float* dst;
    switch (blockIdx.z) {
        case 0: src = W0; dst = g_wt_pre; break;
        case 1: src = W1; dst = g_wt_i;   break;
        case 2: src = W2; dst = g_wt_r;   break;
        case 3: src = W3; dst = g_wt_l;   break;
        default: src = W4; dst = g_wt_r2; break;
    }
    int x = blockIdx.x * 32 + threadIdx.x;
    int y0 = blockIdx.y * 32;
    for (int i = threadIdx.y; i < 32; i += 8)
        t[i][threadIdx.x] = src[(y0 + i) * DIM + x];
    __syncthreads();
    int xo = blockIdx.y * 32 + threadIdx.x;
    int yo0 = blockIdx.x * 32;
    for (int i = threadIdx.y; i < 32; i += 8)
        dst[(yo0 + i) * DIM + xo] = to_tf32(t[threadIdx.x][i]);
}

// ---------------------------------------------------------------------------
// hist + weighted degree (by target)
// ---------------------------------------------------------------------------
__global__ void hist_deg_kernel(const int* __restrict__ ei, const float* __restrict__ ew)
{
    int i = blockIdx.x * blockDim.x + threadIdx.x;
    int stride = gridDim.x * blockDim.x;
    for (; i < E_EDGES; i += stride) {
        int c = ei[E_EDGES + i];
        atomicAdd(&g_hist[c], 1);
        atomicAdd(&g_deg[c], ew[i]);
    }
}

// ---------------------------------------------------------------------------
// single-block exclusive scan over g_hist -> g_rowptr, g_wptr
// ---------------------------------------------------------------------------
__global__ __launch_bounds__(1024) void scan_kernel()
{
    __shared__ int ssum[1024];
    const int CH = (N_NODES + 1023) / 1024;   // 98
    int t = threadIdx.x;
    int lo = t * CH, hi = min(lo + CH, N_NODES);
    int s = 0;
    for (int i = lo; i < hi; ++i) s += g_hist[i];
    ssum[t] = s;
    __syncthreads();
    for (int off = 1; off < 1024; off <<= 1) {
        int v = (t >= off) ? ssum[t - off] : 0;
        __syncthreads();
        if (t >= off) ssum[t] += v;
        __syncthreads();
    }
    int run = (t == 0) ? 0 : ssum[t - 1];
    for (int i = lo; i < hi; ++i) {
        int c = g_hist[i];
        g_rowptr[i] = run;
        g_wptr[i]   = run;
        run += c;
    }
    if (t == 1023) g_rowptr[N_NODES] = run;
}

// ---------------------------------------------------------------------------
// scatter edges into CSR slots; precompute gcn-norm per edge
// ---------------------------------------------------------------------------
__global__ void permute_kernel(const int* __restrict__ ei, const float* __restrict__ ew)
{
    int i = blockIdx.x * blockDim.x + threadIdx.x;
    int stride = gridDim.x * blockDim.x;
    for (; i < E_EDGES; i += stride) {
        int r = ei[i];
        int c = ei[E_EDGES + i];
        float w = ew[i];
        float dr = g_deg[r], dc = g_deg[c];
        float norm = (dr > 0.f && dc > 0.f)
                   ? rsqrtf(fmaxf(dr, 1e-12f)) * w * rsqrtf(fmaxf(dc, 1e-12f)) : 0.f;
        int pos = atomicAdd(&g_wptr[c], 1);
        g_srow[pos] = r;
        g_snw[pos]  = make_float2(norm, w);
    }
}

// ---------------------------------------------------------------------------
// gather: warp per target node; register accumulation; non-atomic writes.
// msg is pre-scaled by 1/max(cnt,1) (mean aggregation folded in).
// ---------------------------------------------------------------------------
__global__ __launch_bounds__(256) void gather_kernel()
{
    int node = (blockIdx.x * blockDim.x + threadIdx.x) >> 5;
    if (node >= N_NODES) return;
    const int lane = threadIdx.x & 31;
    const int beg = g_rowptr[node];
    const int end = g_rowptr[node + 1];

    float4 a = make_float4(0.f, 0.f, 0.f, 0.f);
    float4 m = make_float4(0.f, 0.f, 0.f, 0.f);

    int e = beg;
    for (; e + 1 < end; e += 2) {
        int r0 = g_srow[e], r1 = g_srow[e + 1];
        float2 n0 = g_snw[e], n1 = g_snw[e + 1];
        float4 h0 = ((const float4*)g_h)[r0 * 32 + lane];
        float4 h1 = ((const float4*)g_h)[r1 * 32 + lane];
        a.x += n0.x * h0.x; a.y += n0.x * h0.y; a.z += n0.x * h0.z; a.w += n0.x * h0.w;
        m.x += n0.y * h0.x; m.y += n0.y * h0.y; m.z += n0.y * h0.z; m.w += n0.y * h0.w;
        a.x += n1.x * h1.x; a.y += n1.x * h1.y; a.z += n1.x * h1.z; a.w += n1.x * h1.w;
        m.x += n1.y * h1.x; m.y += n1.y * h1.y; m.z += n1.y * h1.z; m.w += n1.y * h1.w;
    }
    if (e < end) {
        int r0 = g_srow[e];
        float2 n0 = g_snw[e];
        float4 h0 = ((const float4*)g_h)[r0 * 32 + lane];
        a.x += n0.x * h0.x; a.y += n0.x * h0.y; a.z += n0.x * h0.z; a.w += n0.x * h0.w;
        m.x += n0.y * h0.x; m.y += n0.y * h0.y; m.z += n0.y * h0.z; m.w += n0.y * h0.w;
    }

    float rc = 1.f / fmaxf((float)(end - beg), 1.f);
    m.x *= rc; m.y *= rc; m.z *= rc; m.w *= rc;
    ((float4*)g_agg)[node * 32 + lane] = a;
    ((float4*)g_msg)[node * 32 + lane] = m;
}

// ---------------------------------------------------------------------------
// Tensor-core GEMM (tf32 m16n8k8): C[M][128] = A_cat[M][KTOT] @ W + b
//  MODE 2 (KTOT=128): out = g_h, stride 128
//  MODE 0 (KTOT=256): relu epi, out cols [0,128) of 256-stride out
//  MODE 1 (KTOT=256): elu(leaky) epi, cols [128,256)
// ---------------------------------------------------------------------------
template <int KTOT, int MODE>
__global__ __launch_bounds__(256, 2) void gemm_tc(
    const float* __restrict__ A1, const float* __restrict__ WT1,
    const float* __restrict__ A2, const float* __restrict__ WT2,
    const float* __restrict__ bias, float* __restrict__ out)
{
    extern __shared__ float smem[];
    float* As = smem;              // [128][68]
    float* Ws = smem + 128 * 68;   // [128][68]

    const int tid  = threadIdx.x;
    const int row0 = blockIdx.x * 128;
    const int wid  = tid >> 5;
    const int lane = tid & 31;
    const int gid  = lane >> 2;
    const int tig  = lane & 3;
    const int warpM = (wid >> 1) * 32;
    const int warpN = (wid & 1) * 64;

    float acc[2][8][4];
    #pragma unroll
    for (int mt = 0; mt < 2; ++mt)
        #pragma unroll
        for (int nt = 0; nt < 8; ++nt)
            acc[mt][nt][0] = acc[mt][nt][1] = acc[mt][nt][2] = acc[mt][nt][3] = 0.f;

    for (int kc = 0; kc < KTOT; kc += 64) {
        const float* srcA = (KTOT == 256 && kc >= 128) ? A2 : A1;
        const float* srcW = (KTOT == 256 && kc >= 128) ? WT2 : WT1;
        const int koff4 = (kc & 127) >> 2;

        #pragma unroll
        for (int it = 0; it < 8; ++it) {
            int idx = tid + it * 256;
            int r = idx >> 4, j = idx & 15;
            int gr = row0 + r;
            float4 v = make_float4(0.f, 0.f, 0.f, 0.f);
            if (gr < N_NODES)
                v = ((const float4*)srcA)[gr * 32 + koff4 + j];
            v.x = to_tf32(v.x); v.y = to_tf32(v.y);
            v.z = to_tf32(v.z); v.w = to_tf32(v.w);
            *(float4*)&As[r * 68 + j * 4] = v;
        }
        #pragma unroll
        for (int it = 0; it < 8; ++it) {
            int idx = tid + it * 256;
            int n = idx >> 4, j = idx & 15;
            *(float4*)&Ws[n * 68 + j * 4] = ((const float4*)srcW)[n * 32 + koff4 + j];
        }
        __syncthreads();

        #pragma unroll
        for (int k8 = 0; k8 < 64; k8 += 8) {
            float a[2][4];
            #pragma unroll
            for (int mt = 0; mt < 2; ++mt) {
                int rb = warpM + mt * 16 + gid;
                a[mt][0] = As[rb * 68 + k8 + tig];
                a[mt][1] = As[(rb + 8) * 68 + k8 + tig];
                a[mt][2] = As[rb * 68 + k8 + tig + 4];
                a[mt][3] = As[(rb + 8) * 68 + k8 + tig + 4];
            }
            #pragma unroll
            for (int nt = 0; nt < 8; ++nt) {
                int nb = warpN + nt * 8 + gid;
                float b0 = Ws[nb * 68 + k8 + tig];
                float b1 = Ws[nb * 68 + k8 + tig + 4];
                mma_tf32(acc[0][nt], a[0][0], a[0][1], a[0][2], a[0][3], b0, b1);
                mma_tf32(acc[1][nt], a[1][0], a[1][1], a[1][2], a[1][3], b0, b1);
            }
        }
        __syncthreads();
    }

    #pragma unroll
    for (int mt = 0; mt < 2; ++mt) {
        #pragma unroll
        for (int nt = 0; nt < 8; ++nt) {
            int col = warpN + nt * 8 + 2 * tig;
            float2 bb = *(const float2*)&bias[col];
            #pragma unroll
            for (int half = 0; half < 2; ++half) {
                int gr = row0 + warpM + mt * 16 + gid + half * 8;
                if (gr >= N_NODES) continue;
                float v0 = acc[mt][nt][half * 2 + 0] + bb.x;
                float v1 = acc[mt][nt][half * 2 + 1] + bb.y;
                float2 o;
                if (MODE == 0) {
                    o.x = fmaxf(v0, 0.f); o.y = fmaxf(v1, 0.f);
                    *(float2*)&out[gr * 256 + col] = o;
                } else if (MODE == 1) {
                    o.x = v0 > 0.f ? v0 : expm1f(0.01f * v0);
                    o.y = v1 > 0.f ? v1 : expm1f(0.01f * v1);
                    *(float2*)&out[gr * 256 + 128 + col] = o;
                } else {
                    o.x = v0; o.y = v1;
                    *(float2*)&out[gr * 128 + col] = o;
                }
            }
        }
    }
}

// ---------------------------------------------------------------------------
extern "C" void kernel_launch(void* const* d_in, const int* in_sizes, int n_in,
                              void* d_out, int out_size)
{
    const float* x    = (const float*)d_in[0];
    const int*   ei   = (const int*)d_in[1];
    const float* ew   = (const float*)d_in[2];
    const float* Wpre = (const float*)d_in[3];
    const float* bpre = (const float*)d_in[4];
    const float* Wi   = (const float*)d_in[5];
    const float* Wr   = (const float*)d_in[6];
    const float* ba   = (const float*)d_in[7];
    const float* Wl   = (const float*)d_in[8];
    const float* bl   = (const float*)d_in[9];
    const float* Wr2  = (const float*)d_in[10];
    float* out = (float*)d_out;

    void *p_h, *p_agg, *p_msg, *p_deg, *p_hist;
    void *p_wtpre, *p_wti, *p_wtr, *p_wtl, *p_wtr2;
    cudaGetSymbolAddress(&p_h,    g_h);
    cudaGetSymbolAddress(&p_agg,  g_agg);
    cudaGetSymbolAddress(&p_msg,  g_msg);
    cudaGetSymbolAddress(&p_deg,  g_deg);
    cudaGetSymbolAddress(&p_hist, g_hist);
    cudaGetSymbolAddress(&p_wtpre, g_wt_pre);
    cudaGetSymbolAddress(&p_wti,   g_wt_i);
    cudaGetSymbolAddress(&p_wtr,   g_wt_r);
    cudaGetSymbolAddress(&p_wtl,   g_wt_l);
    cudaGetSymbolAddress(&p_wtr2,  g_wt_r2);

    const int SMEM_TC = 2 * 128 * 68 * 4;  // 69,632 B
    cudaFuncSetAttribute(gemm_tc<128,2>, cudaFuncAttributeMaxDynamicSharedMemorySize, SMEM_TC);
    cudaFuncSetAttribute(gemm_tc<256,0>, cudaFuncAttributeMaxDynamicSharedMemorySize, SMEM_TC);
    cudaFuncSetAttribute(gemm_tc<256,1>, cudaFuncAttributeMaxDynamicSharedMemorySize, SMEM_TC);

    cudaMemsetAsync(p_deg,  0, sizeof(float) * N_NODES);
    cudaMemsetAsync(p_hist, 0, sizeof(int)   * N_NODES);

    transpose_weights<<<dim3(4,4,5), dim3(32,8)>>>(Wpre, Wi, Wr, Wl, Wr2);

    const int nblk = (N_NODES + 127) / 128;  // 782

    gemm_tc<128,2><<<nblk, 256, SMEM_TC>>>(x, (const float*)p_wtpre,
                                           nullptr, nullptr, bpre, (float*)p_h);
    hist_deg_kernel<<<1024, 256>>>(ei, ew);
    scan_kernel<<<1, 1024>>>();
    permute_kernel<<<1024, 256>>>(ei, ew);
    gather_kernel<<<(N_NODES * 32 + 255) / 256, 256>>>();
    gemm_tc<256,0><<<nblk, 256, SMEM_TC>>>((const float*)p_agg, (const float*)p_wti,
                                           (const float*)p_h,   (const float*)p_wtr,
                                           ba, out);
    gemm_tc<256,1><<<nblk, 256, SMEM_TC>>>((const float*)p_msg, (const float*)p_wtl,
                                           (const float*)p_h,   (const float*)p_wtr2,
                                           bl, out);
}

// round 6
// speedup vs baseline: 3.1633x; 1.4526x over previous
#include <cuda_runtime.h>
#include <stdint.h>
#include <math.h>

#define N_NODES 100000
#define E_EDGES 1600000
#define DIM 128
#define SCAN_BLK 98   // ceil(100000/1024)

// ---- scratch (device globals: allocation-free) ----
__device__ float g_h  [N_NODES * DIM];   // h = x@W_pre + b
__device__ float g_agg[N_NODES * DIM];   // sum_e norm_e * h[src_e]
__device__ float g_msg[N_NODES * DIM];   // mean_e w_e * h[src_e]
__device__ float g_deg[N_NODES];         // weighted in-degree
__device__ int   g_hist[N_NODES];        // in-edge counts
__device__ int   g_rowptr[N_NODES + 1];  // CSR row pointer (by target)
__device__ int   g_wptr[N_NODES];        // write cursors for permute
__device__ int   g_bsum[SCAN_BLK];       // per-block totals for scan
__device__ int   g_srow[E_EDGES];        // CSR: source node per edge
__device__ float2 g_snw[E_EDGES];        // CSR: (norm, weight) per edge
// transposed + tf32-rounded weights [out][in]
__device__ float g_wt_pre[DIM * DIM];
__device__ float g_wt_i  [DIM * DIM];
__device__ float g_wt_r  [DIM * DIM];
__device__ float g_wt_l  [DIM * DIM];
__device__ float g_wt_r2 [DIM * DIM];

__device__ __forceinline__ float to_tf32(float x) {
    unsigned int u;
    asm("cvt.rna.tf32.f32 %0, %1;" : "=r"(u) : "f"(x));
    return __uint_as_float(u);
}

__device__ __forceinline__ void mma_tf32(float* c, float a0, float a1, float a2, float a3,
                                         float b0, float b1) {
    asm volatile(
        "mma.sync.aligned.m16n8k8.row.col.f32.tf32.tf32.f32 "
        "{%0,%1,%2,%3}, {%4,%5,%6,%7}, {%8,%9}, {%0,%1,%2,%3};"
        : "+f"(c[0]), "+f"(c[1]), "+f"(c[2]), "+f"(c[3])
        : "r"(__float_as_uint(a0)), "r"(__float_as_uint(a1)),
          "r"(__float_as_uint(a2)), "r"(__float_as_uint(a3)),
          "r"(__float_as_uint(b0)), "r"(__float_as_uint(b1)));
}

// ---------------------------------------------------------------------------
// transpose all 5 weights [in][out] -> [out][in], tf32-rounded
// ---------------------------------------------------------------------------
__global__ void transpose_weights(const float* __restrict__ W0, const float* __restrict__ W1,
                                  const float* __restrict__ W2, const float* __restrict__ W3,
                                  const float* __restrict__ W4)
{
    __shared__ float t[32][33];
    const float* src; float* dst;
    switch (blockIdx.z) {
        case 0: src = W0; dst = g_wt_pre; break;
        case 1: src = W1; dst = g_wt_i;   break;
        case 2: src = W2; dst = g_wt_r;   break;
        case 3: src = W3; dst = g_wt_l;   break;
        default: src = W4; dst = g_wt_r2; break;
    }
    int x = blockIdx.x * 32 + threadIdx.x;
    int y0 = blockIdx.y * 32;
    for (int i = threadIdx.y; i < 32; i += 8)
        t[i][threadIdx.x] = src[(y0 + i) * DIM + x];
    __syncthreads();
    int xo = blockIdx.y * 32 + threadIdx.x;
    int yo0 = blockIdx.x * 32;
    for (int i = threadIdx.y; i < 32; i += 8)
        dst[(yo0 + i) * DIM + xo] = to_tf32(t[threadIdx.x][i]);
}

// ---------------------------------------------------------------------------
// hist + weighted degree (by target)
// ---------------------------------------------------------------------------
__global__ void hist_deg_kernel(const int* __restrict__ ei, const float* __restrict__ ew)
{
    int i = blockIdx.x * blockDim.x + threadIdx.x;
    int stride = gridDim.x * blockDim.x;
    for (; i < E_EDGES; i += stride) {
        int c = ei[E_EDGES + i];
        atomicAdd(&g_hist[c], 1);
        atomicAdd(&g_deg[c], ew[i]);
    }
}

// ---------------------------------------------------------------------------
// 3-phase parallel exclusive scan of g_hist -> g_rowptr / g_wptr
// ---------------------------------------------------------------------------
__global__ __launch_bounds__(1024) void scan1_kernel()
{
    __shared__ int wsum[32];
    int t = threadIdx.x;
    int idx = blockIdx.x * 1024 + t;
    int v = (idx < N_NODES) ? g_hist[idx] : 0;

    // inclusive warp scan
    int incl = v;
    #pragma unroll
    for (int off = 1; off < 32; off <<= 1) {
        int n = __shfl_up_sync(0xffffffffu, incl, off);
        if ((t & 31) >= off) incl += n;
    }
    if ((t & 31) == 31) wsum[t >> 5] = incl;
    __syncthreads();
    if (t < 32) {
        int s = wsum[t];
        #pragma unroll
        for (int off = 1; off < 32; off <<= 1) {
            int n = __shfl_up_sync(0xffffffffu, s, off);
            if (t >= off) s += n;
        }
        wsum[t] = s - wsum[t];   // exclusive warp offsets
    }
    __syncthreads();
    int excl = incl - v + wsum[t >> 5];
    if (idx < N_NODES) g_rowptr[idx] = excl;
    if (t == 1023) g_bsum[blockIdx.x] = excl + v;  // block total
}

__global__ void scan2_kernel()
{
    __shared__ int s[128];
    int t = threadIdx.x;
    s[t] = (t < SCAN_BLK) ? g_bsum[t] : 0;
    __syncthreads();
    #pragma unroll
    for (int off = 1; off < 128; off <<= 1) {
        int v = (t >= off) ? s[t - off] : 0;
        __syncthreads();
        s[t] += v;
        __syncthreads();
    }
    if (t < SCAN_BLK) g_bsum[t] = (t == 0) ? 0 : s[t - 1];  // exclusive
}

__global__ __launch_bounds__(1024) void scan3_kernel()
{
    int idx = blockIdx.x * 1024 + threadIdx.x;
    if (idx < N_NODES) {
        int v = g_rowptr[idx] + g_bsum[blockIdx.x];
        g_rowptr[idx] = v;
        g_wptr[idx]   = v;
    }
    if (idx == 0) g_rowptr[N_NODES] = E_EDGES;
}

// ---------------------------------------------------------------------------
// scatter edges into CSR slots; precompute gcn-norm per edge
// ---------------------------------------------------------------------------
__global__ void permute_kernel(const int* __restrict__ ei, const float* __restrict__ ew)
{
    int i = blockIdx.x * blockDim.x + threadIdx.x;
    int stride = gridDim.x * blockDim.x;
    for (; i < E_EDGES; i += stride) {
        int r = ei[i];
        int c = ei[E_EDGES + i];
        float w = ew[i];
        float dr = g_deg[r], dc = g_deg[c];
        float norm = (dr > 0.f && dc > 0.f)
                   ? rsqrtf(fmaxf(dr, 1e-12f)) * w * rsqrtf(fmaxf(dc, 1e-12f)) : 0.f;
        int pos = atomicAdd(&g_wptr[c], 1);
        g_srow[pos] = r;
        g_snw[pos]  = make_float2(norm, w);
    }
}

// ---------------------------------------------------------------------------
// gather: warp per target node; register accumulation; non-atomic writes.
// msg pre-scaled by 1/max(cnt,1) (mean aggregation folded in).
// ---------------------------------------------------------------------------
__global__ __launch_bounds__(256) void gather_kernel()
{
    int node = (blockIdx.x * blockDim.x + threadIdx.x) >> 5;
    if (node >= N_NODES) return;
    const int lane = threadIdx.x & 31;
    const int beg = g_rowptr[node];
    const int end = g_rowptr[node + 1];

    float4 a = make_float4(0.f, 0.f, 0.f, 0.f);
    float4 m = make_float4(0.f, 0.f, 0.f, 0.f);

    int e = beg;
    for (; e + 1 < end; e += 2) {
        int r0 = g_srow[e], r1 = g_srow[e + 1];
        float2 n0 = g_snw[e], n1 = g_snw[e + 1];
        float4 h0 = ((const float4*)g_h)[r0 * 32 + lane];
        float4 h1 = ((const float4*)g_h)[r1 * 32 + lane];
        a.x += n0.x * h0.x; a.y += n0.x * h0.y; a.z += n0.x * h0.z; a.w += n0.x * h0.w;
        m.x += n0.y * h0.x; m.y += n0.y * h0.y; m.z += n0.y * h0.z; m.w += n0.y * h0.w;
        a.x += n1.x * h1.x; a.y += n1.x * h1.y; a.z += n1.x * h1.z; a.w += n1.x * h1.w;
        m.x += n1.y * h1.x; m.y += n1.y * h1.y; m.z += n1.y * h1.z; m.w += n1.y * h1.w;
    }
    if (e < end) {
        int r0 = g_srow[e];
        float2 n0 = g_snw[e];
        float4 h0 = ((const float4*)g_h)[r0 * 32 + lane];
        a.x += n0.x * h0.x; a.y += n0.x * h0.y; a.z += n0.x * h0.z; a.w += n0.x * h0.w;
        m.x += n0.y * h0.x; m.y += n0.y * h0.y; m.z += n0.y * h0.z; m.w += n0.y * h0.w;
    }

    float rc = 1.f / fmaxf((float)(end - beg), 1.f);
    m.x *= rc; m.y *= rc; m.z *= rc; m.w *= rc;
    ((float4*)g_agg)[node * 32 + lane] = a;
    ((float4*)g_msg)[node * 32 + lane] = m;
}

// ---------------------------------------------------------------------------
// Tensor-core GEMM (tf32 m16n8k8): C[M][128] = A_cat[M][KTOT] @ W + b
// ---------------------------------------------------------------------------
template <int KTOT, int MODE>
__global__ __launch_bounds__(256, 2) void gemm_tc(
    const float* __restrict__ A1, const float* __restrict__ WT1,
    const float* __restrict__ A2, const float* __restrict__ WT2,
    const float* __restrict__ bias, float* __restrict__ out)
{
    extern __shared__ float smem[];
    float* As = smem;              // [128][68]
    float* Ws = smem + 128 * 68;   // [128][68]

    const int tid  = threadIdx.x;
    const int row0 = blockIdx.x * 128;
    const int wid  = tid >> 5;
    const int lane = tid & 31;
    const int gid  = lane >> 2;
    const int tig  = lane & 3;
    const int warpM = (wid >> 1) * 32;
    const int warpN = (wid & 1) * 64;

    float acc[2][8][4];
    #pragma unroll
    for (int mt = 0; mt < 2; ++mt)
        #pragma unroll
        for (int nt = 0; nt < 8; ++nt)
            acc[mt][nt][0] = acc[mt][nt][1] = acc[mt][nt][2] = acc[mt][nt][3] = 0.f;

    for (int kc = 0; kc < KTOT; kc += 64) {
        const float* srcA = (KTOT == 256 && kc >= 128) ? A2 : A1;
        const float* srcW = (KTOT == 256 && kc >= 128) ? WT2 : WT1;
        const int koff4 = (kc & 127) >> 2;

        #pragma unroll
        for (int it = 0; it < 8; ++it) {
            int idx = tid + it * 256;
            int r = idx >> 4, j = idx & 15;
            int gr = row0 + r;
            float4 v = make_float4(0.f, 0.f, 0.f, 0.f);
            if (gr < N_NODES)
                v = ((const float4*)srcA)[gr * 32 + koff4 + j];
            v.x = to_tf32(v.x); v.y = to_tf32(v.y);
            v.z = to_tf32(v.z); v.w = to_tf32(v.w);
            *(float4*)&As[r * 68 + j * 4] = v;
        }
        #pragma unroll
        for (int it = 0; it < 8; ++it) {
            int idx = tid + it * 256;
            int n = idx >> 4, j = idx & 15;
            *(float4*)&Ws[n * 68 + j * 4] = ((const float4*)srcW)[n * 32 + koff4 + j];
        }
        __syncthreads();

        #pragma unroll
        for (int k8 = 0; k8 < 64; k8 += 8) {
            float a[2][4];
            #pragma unroll
            for (int mt = 0; mt < 2; ++mt) {
                int rb = warpM + mt * 16 + gid;
                a[mt][0] = As[rb * 68 + k8 + tig];
                a[mt][1] = As[(rb + 8) * 68 + k8 + tig];
                a[mt][2] = As[rb * 68 + k8 + tig + 4];
                a[mt][3] = As[(rb + 8) * 68 + k8 + tig + 4];
            }
            #pragma unroll
            for (int nt = 0; nt < 8; ++nt) {
                int nb = warpN + nt * 8 + gid;
                float b0 = Ws[nb * 68 + k8 + tig];
                float b1 = Ws[nb * 68 + k8 + tig + 4];
                mma_tf32(acc[0][nt], a[0][0], a[0][1], a[0][2], a[0][3], b0, b1);
                mma_tf32(acc[1][nt], a[1][0], a[1][1], a[1][2], a[1][3], b0, b1);
            }
        }
        __syncthreads();
    }

    #pragma unroll
    for (int mt = 0; mt < 2; ++mt) {
        #pragma unroll
        for (int nt = 0; nt < 8; ++nt) {
            int col = warpN + nt * 8 + 2 * tig;
            float2 bb = *(const float2*)&bias[col];
            #pragma unroll
            for (int half = 0; half < 2; ++half) {
                int gr = row0 + warpM + mt * 16 + gid + half * 8;
                if (gr >= N_NODES) continue;
                float v0 = acc[mt][nt][half * 2 + 0] + bb.x;
                float v1 = acc[mt][nt][half * 2 + 1] + bb.y;
                float2 o;
                if (MODE == 0) {
                    o.x = fmaxf(v0, 0.f); o.y = fmaxf(v1, 0.f);
                    *(float2*)&out[gr * 256 + col] = o;
                } else if (MODE == 1) {
                    o.x = v0 > 0.f ? v0 : expm1f(0.01f * v0);
                    o.y = v1 > 0.f ? v1 : expm1f(0.01f * v1);
                    *(float2*)&out[gr * 256 + 128 + col] = o;
                } else {
                    o.x = v0; o.y = v1;
                    *(float2*)&out[gr * 128 + col] = o;
                }
            }
        }
    }
}

// ---------------------------------------------------------------------------
extern "C" void kernel_launch(void* const* d_in, const int* in_sizes, int n_in,
                              void* d_out, int out_size)
{
    const float* x    = (const float*)d_in[0];
    const int*   ei   = (const int*)d_in[1];
    const float* ew   = (const float*)d_in[2];
    const float* Wpre = (const float*)d_in[3];
    const float* bpre = (const float*)d_in[4];
    const float* Wi   = (const float*)d_in[5];
    const float* Wr   = (const float*)d_in[6];
    const float* ba   = (const float*)d_in[7];
    const float* Wl   = (const float*)d_in[8];
    const float* bl   = (const float*)d_in[9];
    const float* Wr2  = (const float*)d_in[10];
    float* out = (float*)d_out;

    void *p_h, *p_agg, *p_msg, *p_deg, *p_hist;
    void *p_wtpre, *p_wti, *p_wtr, *p_wtl, *p_wtr2;
    cudaGetSymbolAddress(&p_h,    g_h);
    cudaGetSymbolAddress(&p_agg,  g_agg);
    cudaGetSymbolAddress(&p_msg,  g_msg);
    cudaGetSymbolAddress(&p_deg,  g_deg);
    cudaGetSymbolAddress(&p_hist, g_hist);
    cudaGetSymbolAddress(&p_wtpre, g_wt_pre);
    cudaGetSymbolAddress(&p_wti,   g_wt_i);
    cudaGetSymbolAddress(&p_wtr,   g_wt_r);
    cudaGetSymbolAddress(&p_wtl,   g_wt_l);
    cudaGetSymbolAddress(&p_wtr2,  g_wt_r2);

    const int SMEM_TC = 2 * 128 * 68 * 4;  // 69,632 B
    cudaFuncSetAttribute(gemm_tc<128,2>, cudaFuncAttributeMaxDynamicSharedMemorySize, SMEM_TC);
    cudaFuncSetAttribute(gemm_tc<256,0>, cudaFuncAttributeMaxDynamicSharedMemorySize, SMEM_TC);
    cudaFuncSetAttribute(gemm_tc<256,1>, cudaFuncAttributeMaxDynamicSharedMemorySize, SMEM_TC);

    cudaMemsetAsync(p_deg,  0, sizeof(float) * N_NODES);
    cudaMemsetAsync(p_hist, 0, sizeof(int)   * N_NODES);

    transpose_weights<<<dim3(4,4,5), dim3(32,8)>>>(Wpre, Wi, Wr, Wl, Wr2);

    const int nblk = (N_NODES + 127) / 128;  // 782

    gemm_tc<128,2><<<nblk, 256, SMEM_TC>>>(x, (const float*)p_wtpre,
                                           nullptr, nullptr, bpre, (float*)p_h);
    hist_deg_kernel<<<1024, 256>>>(ei, ew);
    scan1_kernel<<<SCAN_BLK, 1024>>>();
    scan2_kernel<<<1, 128>>>();
    scan3_kernel<<<SCAN_BLK, 1024>>>();
    permute_kernel<<<1024, 256>>>(ei, ew);
    gather_kernel<<<(N_NODES * 32 + 255) / 256, 256>>>();
    gemm_tc<256,0><<<nblk, 256, SMEM_TC>>>((const float*)p_agg, (const float*)p_wti,
                                           (const float*)p_h,   (const float*)p_wtr,
                                           ba, out);
    gemm_tc<256,1><<<nblk, 256, SMEM_TC>>>((const float*)p_msg, (const float*)p_wtl,
                                           (const float*)p_h,   (const float*)p_wtr2,
                                           bl, out);
}

// round 9
// speedup vs baseline: 3.3520x; 1.0597x over previous
#include <cuda_runtime.h>
#include <stdint.h>
#include <math.h>

#define N_NODES 100000
#define E_EDGES 1600000
#define DIM 128
#define SCAN_BLK 98   // ceil(100000/1024)

// ---- scratch (device globals: allocation-free) ----
__device__ float g_h  [N_NODES * DIM];   // h = x@W_pre + b   (tf32-rounded)
__device__ float g_agg[N_NODES * DIM];   // tf32-rounded
__device__ float g_msg[N_NODES * DIM];   // tf32-rounded, mean-scaled
__device__ float g_deg[N_NODES];
__device__ int   g_hist[N_NODES];
__device__ int   g_rowptr[N_NODES + 1];
__device__ int   g_wptr[N_NODES];
__device__ int   g_bsum[SCAN_BLK];
__device__ int   g_srow[E_EDGES];
__device__ float2 g_snw[E_EDGES];
// transposed + tf32-rounded weights [out][in]
__device__ float g_wt_pre[DIM * DIM];
__device__ float g_wt_i  [DIM * DIM];
__device__ float g_wt_r  [DIM * DIM];
__device__ float g_wt_l  [DIM * DIM];
__device__ float g_wt_r2 [DIM * DIM];

__device__ __forceinline__ float to_tf32(float x) {
    unsigned int u;
    asm("cvt.rna.tf32.f32 %0, %1;" : "=r"(u) : "f"(x));
    return __uint_as_float(u);
}

__device__ __forceinline__ void mma_tf32(float* c, float a0, float a1, float a2, float a3,
                                         float b0, float b1) {
    asm volatile(
        "mma.sync.aligned.m16n8k8.row.col.f32.tf32.tf32.f32 "
        "{%0,%1,%2,%3}, {%4,%5,%6,%7}, {%8,%9}, {%0,%1,%2,%3};"
        : "+f"(c[0]), "+f"(c[1]), "+f"(c[2]), "+f"(c[3])
        : "r"(__float_as_uint(a0)), "r"(__float_as_uint(a1)),
          "r"(__float_as_uint(a2)), "r"(__float_as_uint(a3)),
          "r"(__float_as_uint(b0)), "r"(__float_as_uint(b1)));
}

__device__ __forceinline__ void cp16(float* dst_smem, const float* src) {
    unsigned int sa = (unsigned int)__cvta_generic_to_shared(dst_smem);
    asm volatile("cp.async.cg.shared.global [%0], [%1], 16;" :: "r"(sa), "l"(src));
}

// ---------------------------------------------------------------------------
// transpose all 5 weights [in][out] -> [out][in], tf32-rounded
// ---------------------------------------------------------------------------
__global__ void transpose_weights(const float* __restrict__ W0, const float* __restrict__ W1,
                                  const float* __restrict__ W2, const float* __restrict__ W3,
                                  const float* __restrict__ W4)
{
    __shared__ float t[32][33];
    const float* src; float* dst;
    switch (blockIdx.z) {
        case 0: src = W0; dst = g_wt_pre; break;
        case 1: src = W1; dst = g_wt_i;   break;
        case 2: src = W2; dst = g_wt_r;   break;
        case 3: src = W3; dst = g_wt_l;   break;
        default: src = W4; dst = g_wt_r2; break;
    }
    int x = blockIdx.x * 32 + threadIdx.x;
    int y0 = blockIdx.y * 32;
    for (int i = threadIdx.y; i < 32; i += 8)
        t[i][threadIdx.x] = src[(y0 + i) * DIM + x];
    __syncthreads();
    int xo = blockIdx.y * 32 + threadIdx.x;
    int yo0 = blockIdx.x * 32;
    for (int i = threadIdx.y; i < 32; i += 8)
        dst[(yo0 + i) * DIM + xo] = to_tf32(t[threadIdx.x][i]);
}

// ---------------------------------------------------------------------------
// hist + weighted degree (by target)
// ---------------------------------------------------------------------------
__global__ void hist_deg_kernel(const int* __restrict__ ei, const float* __restrict__ ew)
{
    int i = blockIdx.x * blockDim.x + threadIdx.x;
    int stride = gridDim.x * blockDim.x;
    for (; i < E_EDGES; i += stride) {
        int c = ei[E_EDGES + i];
        atomicAdd(&g_hist[c], 1);
        atomicAdd(&g_deg[c], ew[i]);
    }
}

// ---------------------------------------------------------------------------
// 3-phase parallel exclusive scan of g_hist -> g_rowptr / g_wptr
// ---------------------------------------------------------------------------
__global__ __launch_bounds__(1024) void scan1_kernel()
{
    __shared__ int wsum[32];
    int t = threadIdx.x;
    int idx = blockIdx.x * 1024 + t;
    int v = (idx < N_NODES) ? g_hist[idx] : 0;

    int incl = v;
    #pragma unroll
    for (int off = 1; off < 32; off <<= 1) {
        int n = __shfl_up_sync(0xffffffffu, incl, off);
        if ((t & 31) >= off) incl += n;
    }
    if ((t & 31) == 31) wsum[t >> 5] = incl;
    __syncthreads();
    if (t < 32) {
        int s = wsum[t];
        #pragma unroll
        for (int off = 1; off < 32; off <<= 1) {
            int n = __shfl_up_sync(0xffffffffu, s, off);
            if (t >= off) s += n;
        }
        wsum[t] = s - wsum[t];
    }
    __syncthreads();
    int excl = incl - v + wsum[t >> 5];
    if (idx < N_NODES) g_rowptr[idx] = excl;
    if (t == 1023) g_bsum[blockIdx.x] = excl + v;
}

__global__ void scan2_kernel()
{
    __shared__ int s[128];
    int t = threadIdx.x;
    s[t] = (t < SCAN_BLK) ? g_bsum[t] : 0;
    __syncthreads();
    #pragma unroll
    for (int off = 1; off < 128; off <<= 1) {
        int v = (t >= off) ? s[t - off] : 0;
        __syncthreads();
        s[t] += v;
        __syncthreads();
    }
    if (t < SCAN_BLK) g_bsum[t] = (t == 0) ? 0 : s[t - 1];
}

__global__ __launch_bounds__(1024) void scan3_kernel()
{
    int idx = blockIdx.x * 1024 + threadIdx.x;
    if (idx < N_NODES) {
        int v = g_rowptr[idx] + g_bsum[blockIdx.x];
        g_rowptr[idx] = v;
        g_wptr[idx]   = v;
    }
    if (idx == 0) g_rowptr[N_NODES] = E_EDGES;
}

// ---------------------------------------------------------------------------
// scatter edges into CSR slots; precompute gcn-norm per edge
// ---------------------------------------------------------------------------
__global__ void permute_kernel(const int* __restrict__ ei, const float* __restrict__ ew)
{
    int i = blockIdx.x * blockDim.x + threadIdx.x;
    int stride = gridDim.x * blockDim.x;
    for (; i < E_EDGES; i += stride) {
        int r = ei[i];
        int c = ei[E_EDGES + i];
        float w = ew[i];
        float dr = g_deg[r], dc = g_deg[c];
        float norm = (dr > 0.f && dc > 0.f)
                   ? rsqrtf(fmaxf(dr, 1e-12f)) * w * rsqrtf(fmaxf(dc, 1e-12f)) : 0.f;
        int pos = atomicAdd(&g_wptr[c], 1);
        g_srow[pos] = r;
        g_snw[pos]  = make_float2(norm, w);
    }
}

// ---------------------------------------------------------------------------
// gather: warp per target node; outputs tf32-rounded (GEMMs skip cvt)
// ---------------------------------------------------------------------------
__global__ __launch_bounds__(256) void gather_kernel()
{
    int node = (blockIdx.x * blockDim.x + threadIdx.x) >> 5;
    if (node >= N_NODES) return;
    const int lane = threadIdx.x & 31;
    const int beg = g_rowptr[node];
    const int end = g_rowptr[node + 1];

    float4 a = make_float4(0.f, 0.f, 0.f, 0.f);
    float4 m = make_float4(0.f, 0.f, 0.f, 0.f);

    int e = beg;
    for (; e + 1 < end; e += 2) {
        int r0 = g_srow[e], r1 = g_srow[e + 1];
        float2 n0 = g_snw[e], n1 = g_snw[e + 1];
        float4 h0 = ((const float4*)g_h)[r0 * 32 + lane];
        float4 h1 = ((const float4*)g_h)[r1 * 32 + lane];
        a.x += n0.x * h0.x; a.y += n0.x * h0.y; a.z += n0.x * h0.z; a.w += n0.x * h0.w;
        m.x += n0.y * h0.x; m.y += n0.y * h0.y; m.z += n0.y * h0.z; m.w += n0.y * h0.w;
        a.x += n1.x * h1.x; a.y += n1.x * h1.y; a.z += n1.x * h1.z; a.w += n1.x * h1.w;
        m.x += n1.y * h1.x; m.y += n1.y * h1.y; m.z += n1.y * h1.z; m.w += n1.y * h1.w;
    }
    if (e < end) {
        int r0 = g_srow[e];
        float2 n0 = g_snw[e];
        float4 h0 = ((const float4*)g_h)[r0 * 32 + lane];
        a.x += n0.x * h0.x; a.y += n0.x * h0.y; a.z += n0.x * h0.z; a.w += n0.x * h0.w;
        m.x += n0.y * h0.x; m.y += n0.y * h0.y; m.z += n0.y * h0.z; m.w += n0.y * h0.w;
    }

    float rc = 1.f / fmaxf((float)(end - beg), 1.f);
    float4 ao = make_float4(to_tf32(a.x), to_tf32(a.y), to_tf32(a.z), to_tf32(a.w));
    float4 mo = make_float4(to_tf32(m.x * rc), to_tf32(m.y * rc),
                            to_tf32(m.z * rc), to_tf32(m.w * rc));
    ((float4*)g_agg)[node * 32 + lane] = ao;
    ((float4*)g_msg)[node * 32 + lane] = mo;
}

// ---------------------------------------------------------------------------
// cp.async double-buffered tf32 GEMM.
// C[M][128] = A_cat[M][KTOT] @ W + b.  K chunks of 32, 2-stage pipeline.
// smem: As[2][128*36] + Ws[2][128*36] = 73,728 B  -> 2 CTAs/SM.
//  MODE 2 (KTOT=128, CVT_A=1): out = g_h (tf32-rounded), stride 128
//  MODE 0 (KTOT=256): relu epi, out cols [0,128) of 256-stride out
//  MODE 1 (KTOT=256): elu(leaky) epi, cols [128,256)
// ---------------------------------------------------------------------------
template <int KTOT, int MODE, int CVT_A>
__global__ __launch_bounds__(256, 2) void gemm_tc(
    const float* __restrict__ A1, const float* __restrict__ WT1,
    const float* __restrict__ A2, const float* __restrict__ WT2,
    const float* __restrict__ bias, float* __restrict__ out)
{
    extern __shared__ float smem[];
    const int CH = 128 * 36;
    float* As = smem;            // [2][128][36]
    float* Ws = smem + 2 * CH;   // [2][128][36]

    const int tid  = threadIdx.x;
    const int row0 = blockIdx.x * 128;
    const int wid  = tid >> 5;
    const int lane = tid & 31;
    const int gid  = lane >> 2;
    const int tig  = lane & 3;
    const int warpM = (wid >> 1) * 32;
    const int warpN = (wid & 1) * 64;
    const int NC = KTOT / 32;

    // staging task for this thread: 4 A-rows + 4 W-rows of float4
    int sr[4], sj[4], sgr[4];
    #pragma unroll
    for (int it = 0; it < 4; ++it) {
        int idx = tid + it * 256;           // [0,1024)
        sr[it] = idx >> 3;                  // row 0..127
        sj[it] = idx & 7;                   // float4 col 0..7
        int gr = row0 + sr[it];
        sgr[it] = gr < N_NODES ? gr : N_NODES - 1;   // clamp (rows >= N unused)
    }

    auto stage = [&](int c, int buf) {
        const float* srcA = (KTOT == 256 && c >= 4) ? A2 : A1;
        const float* srcW = (KTOT == 256 && c >= 4) ? WT2 : WT1;
        const int kf = (c & 3) * 32;        // float offset within 128-wide row
        #pragma unroll
        for (int it = 0; it < 4; ++it)
            cp16(&As[buf * CH + sr[it] * 36 + sj[it] * 4],
                 &srcA[sgr[it] * DIM + kf + sj[it] * 4]);
        #pragma unroll
        for (int it = 0; it < 4; ++it)
            cp16(&Ws[buf * CH + sr[it] * 36 + sj[it] * 4],
                 &srcW[sr[it] * DIM + kf + sj[it] * 4]);
        asm volatile("cp.async.commit_group;");
    };

    float acc[2][8][4];
    #pragma unroll
    for (int mt = 0; mt < 2; ++mt)
        #pragma unroll
        for (int nt = 0; nt < 8; ++nt)
            acc[mt][nt][0] = acc[mt][nt][1] = acc[mt][nt][2] = acc[mt][nt][3] = 0.f;

    stage(0, 0);

    for (int c = 0; c < NC; ++c) {
        if (c + 1 < NC) {
            stage(c + 1, (c + 1) & 1);
            asm volatile("cp.async.wait_group 1;");
        } else {
            asm volatile("cp.async.wait_group 0;");
        }
        __syncthreads();

        const float* Ab = &As[(c & 1) * CH];
        const float* Wb = &Ws[(c & 1) * CH];
        #pragma unroll
        for (int k8 = 0; k8 < 32; k8 += 8) {
            float a[2][4];
            #pragma unroll
            for (int mt = 0; mt < 2; ++mt) {
                int rb = warpM + mt * 16 + gid;
                a[mt][0] = Ab[rb * 36 + k8 + tig];
                a[mt][1] = Ab[(rb + 8) * 36 + k8 + tig];
                a[mt][2] = Ab[rb * 36 + k8 + tig + 4];
                a[mt][3] = Ab[(rb + 8) * 36 + k8 + tig + 4];
                if (CVT_A) {
                    a[mt][0] = to_tf32(a[mt][0]); a[mt][1] = to_tf32(a[mt][1]);
                    a[mt][2] = to_tf32(a[mt][2]); a[mt][3] = to_tf32(a[mt][3]);
                }
            }
            #pragma unroll
            for (int nt = 0; nt < 8; ++nt) {
                int nb = warpN + nt * 8 + gid;
                float b0 = Wb[nb * 36 + k8 + tig];
                float b1 = Wb[nb * 36 + k8 + tig + 4];
                mma_tf32(acc[0][nt], a[0][0], a[0][1], a[0][2], a[0][3], b0, b1);
                mma_tf32(acc[1][nt], a[1][0], a[1][1], a[1][2], a[1][3], b0, b1);
            }
        }
        __syncthreads();
    }

    #pragma unroll
    for (int mt = 0; mt < 2; ++mt) {
        #pragma unroll
        for (int nt = 0; nt < 8; ++nt) {
            int col = warpN + nt * 8 + 2 * tig;
            float2 bb = *(const float2*)&bias[col];
            #pragma unroll
            for (int half = 0; half < 2; ++half) {
                int gr = row0 + warpM + mt * 16 + gid + half * 8;
                if (gr >= N_NODES) continue;
                float v0 = acc[mt][nt][half * 2 + 0] + bb.x;
                float v1 = acc[mt][nt][half * 2 + 1] + bb.y;
                float2 o;
                if (MODE == 0) {
                    o.x = fmaxf(v0, 0.f); o.y = fmaxf(v1, 0.f);
                    *(float2*)&out[gr * 256 + col] = o;
                } else if (MODE == 1) {
                    o.x = v0 > 0.f ? v0 : expm1f(0.01f * v0);
                    o.y = v1 > 0.f ? v1 : expm1f(0.01f * v1);
                    *(float2*)&out[gr * 256 + 128 + col] = o;
                } else {
                    o.x = to_tf32(v0); o.y = to_tf32(v1);   // pre-round h
                    *(float2*)&out[gr * 128 + col] = o;
                }
            }
        }
    }
}

// ---------------------------------------------------------------------------
extern "C" void kernel_launch(void* const* d_in, const int* in_sizes, int n_in,
                              void* d_out, int out_size)
{
    const float* x    = (const float*)d_in[0];
    const int*   ei   = (const int*)d_in[1];
    const float* ew   = (const float*)d_in[2];
    const float* Wpre = (const float*)d_in[3];
    const float* bpre = (const float*)d_in[4];
    const float* Wi   = (const float*)d_in[5];
    const float* Wr   = (const float*)d_in[6];
    const float* ba   = (const float*)d_in[7];
    const float* Wl   = (const float*)d_in[8];
    const float* bl   = (const float*)d_in[9];
    const float* Wr2  = (const float*)d_in[10];
    float* out = (float*)d_out;

    void *p_h, *p_agg, *p_msg, *p_deg, *p_hist;
    void *p_wtpre, *p_wti, *p_wtr, *p_wtl, *p_wtr2;
    cudaGetSymbolAddress(&p_h,    g_h);
    cudaGetSymbolAddress(&p_agg,  g_agg);
    cudaGetSymbolAddress(&p_msg,  g_msg);
    cudaGetSymbolAddress(&p_deg,  g_deg);
    cudaGetSymbolAddress(&p_hist, g_hist);
    cudaGetSymbolAddress(&p_wtpre, g_wt_pre);
    cudaGetSymbolAddress(&p_wti,   g_wt_i);
    cudaGetSymbolAddress(&p_wtr,   g_wt_r);
    cudaGetSymbolAddress(&p_wtl,   g_wt_l);
    cudaGetSymbolAddress(&p_wtr2,  g_wt_r2);

    const int SMEM_TC = 4 * 128 * 36 * 4;  // 73,728 B
    cudaFuncSetAttribute(gemm_tc<128,2,1>, cudaFuncAttributeMaxDynamicSharedMemorySize, SMEM_TC);
    cudaFuncSetAttribute(gemm_tc<256,0,0>, cudaFuncAttributeMaxDynamicSharedMemorySize, SMEM_TC);
    cudaFuncSetAttribute(gemm_tc<256,1,0>, cudaFuncAttributeMaxDynamicSharedMemorySize, SMEM_TC);

    cudaMemsetAsync(p_deg,  0, sizeof(float) * N_NODES);
    cudaMemsetAsync(p_hist, 0, sizeof(int)   * N_NODES);

    transpose_weights<<<dim3(4,4,5), dim3(32,8)>>>(Wpre, Wi, Wr, Wl, Wr2);

    const int nblk = (N_NODES + 127) / 128;  // 782

    gemm_tc<128,2,1><<<nblk, 256, SMEM_TC>>>(x, (const float*)p_wtpre,
                                             nullptr, nullptr, bpre, (float*)p_h);
    hist_deg_kernel<<<1024, 256>>>(ei, ew);
    scan1_kernel<<<SCAN_BLK, 1024>>>();
    scan2_kernel<<<1, 128>>>();
    scan3_kernel<<<SCAN_BLK, 1024>>>();
    permute_kernel<<<1024, 256>>>(ei, ew);
    gather_kernel<<<(N_NODES * 32 + 255) / 256, 256>>>();
    gemm_tc<256,0,0><<<nblk, 256, SMEM_TC>>>((const float*)p_agg, (const float*)p_wti,
                                             (const float*)p_h,   (const float*)p_wtr,
                                             ba, out);
    gemm_tc<256,1,0><<<nblk, 256, SMEM_TC>>>((const float*)p_msg, (const float*)p_wtl,
                                             (const float*)p_h,   (const float*)p_wtr2,
                                             bl, out);
}

// round 13
// speedup vs baseline: 4.2770x; 1.2759x over previous
#include <cuda_runtime.h>
#include <cuda_fp16.h>
#include <stdint.h>
#include <math.h>

#define N_NODES 100000
#define E_EDGES 1600000
#define DIM 128
#define SCAN_BLK 98   // ceil(100000/1024)

// ---- scratch (device globals: allocation-free) ----
__device__ __half g_h16 [N_NODES * DIM];  // h, fp16
__device__ __half g_agg16[N_NODES * DIM]; // fp16
__device__ __half g_msg16[N_NODES * DIM]; // fp16, mean-scaled
__device__ float g_deg[N_NODES];
__device__ int   g_hist[N_NODES];
__device__ int   g_rowptr[N_NODES + 1];
__device__ int   g_wptr[N_NODES];
__device__ int   g_bsum[SCAN_BLK];
__device__ int   g_srow[E_EDGES];
__device__ float2 g_snw[E_EDGES];
// transposed weights [out][in]
__device__ float  g_wt_pre[DIM * DIM];            // tf32-rounded fp32
__device__ __half g_wt16_i [DIM * DIM];
__device__ __half g_wt16_r [DIM * DIM];
__device__ __half g_wt16_l [DIM * DIM];
__device__ __half g_wt16_r2[DIM * DIM];

// ---------------------------------------------------------------------------
// helpers
// ---------------------------------------------------------------------------
__device__ __forceinline__ float to_tf32(float x) {
    unsigned int u;
    asm("cvt.rna.tf32.f32 %0, %1;" : "=r"(u) : "f"(x));
    return __uint_as_float(u);
}

__device__ __forceinline__ void mma_tf32(float* c, float a0, float a1, float a2, float a3,
                                         float b0, float b1) {
    asm volatile(
        "mma.sync.aligned.m16n8k8.row.col.f32.tf32.tf32.f32 "
        "{%0,%1,%2,%3}, {%4,%5,%6,%7}, {%8,%9}, {%0,%1,%2,%3};"
        : "+f"(c[0]), "+f"(c[1]), "+f"(c[2]), "+f"(c[3])
        : "r"(__float_as_uint(a0)), "r"(__float_as_uint(a1)),
          "r"(__float_as_uint(a2)), "r"(__float_as_uint(a3)),
          "r"(__float_as_uint(b0)), "r"(__float_as_uint(b1)));
}

__device__ __forceinline__ void mma_f16(float* c, unsigned int a0, unsigned int a1,
                                        unsigned int a2, unsigned int a3,
                                        unsigned int b0, unsigned int b1) {
    asm volatile(
        "mma.sync.aligned.m16n8k16.row.col.f32.f16.f16.f32 "
        "{%0,%1,%2,%3}, {%4,%5,%6,%7}, {%8,%9}, {%0,%1,%2,%3};"
        : "+f"(c[0]), "+f"(c[1]), "+f"(c[2]), "+f"(c[3])
        : "r"(a0), "r"(a1), "r"(a2), "r"(a3), "r"(b0), "r"(b1));
}

__device__ __forceinline__ void ldsm_x4(unsigned int& r0, unsigned int& r1,
                                        unsigned int& r2, unsigned int& r3,
                                        unsigned int addr) {
    asm volatile("ldmatrix.sync.aligned.m8n8.x4.shared.b16 {%0,%1,%2,%3}, [%4];"
                 : "=r"(r0), "=r"(r1), "=r"(r2), "=r"(r3) : "r"(addr));
}

__device__ __forceinline__ void cp16(void* dst_smem, const void* src) {
    unsigned int sa = (unsigned int)__cvta_generic_to_shared(dst_smem);
    asm volatile("cp.async.cg.shared.global [%0], [%1], 16;" :: "r"(sa), "l"(src));
}

__device__ __forceinline__ unsigned int smem_u32(const void* p) {
    unsigned int a;
    asm("{ .reg .u64 t; cvta.to.shared.u64 t, %1; cvt.u32.u64 %0, t; }"
        : "=r"(a) : "l"(p));
    return a;
}

#define SMEM_SWIZZLE_128B(byte_offset) \
    ((byte_offset) ^ (((byte_offset) >> 3) & 0x70))

// ---------------------------------------------------------------------------
// transpose weights: Wpre -> fp32 tf32-rounded; others -> fp16. [in][out]->[out][in]
// ---------------------------------------------------------------------------
__global__ void transpose_weights(const float* __restrict__ W0, const float* __restrict__ W1,
                                  const float* __restrict__ W2, const float* __restrict__ W3,
                                  const float* __restrict__ W4)
{
    __shared__ float t[32][33];
    const float* src;
    switch (blockIdx.z) {
        case 0: src = W0; break;
        case 1: src = W1; break;
        case 2: src = W2; break;
        case 3: src = W3; break;
        default: src = W4; break;
    }
    int x = blockIdx.x * 32 + threadIdx.x;
    int y0 = blockIdx.y * 32;
    for (int i = threadIdx.y; i < 32; i += 8)
        t[i][threadIdx.x] = src[(y0 + i) * DIM + x];
    __syncthreads();
    int xo = blockIdx.y * 32 + threadIdx.x;
    int yo0 = blockIdx.x * 32;
    if (blockIdx.z == 0) {
        for (int i = threadIdx.y; i < 32; i += 8)
            g_wt_pre[(yo0 + i) * DIM + xo] = to_tf32(t[threadIdx.x][i]);
    } else {
        __half* dst;
        switch (blockIdx.z) {
            case 1: dst = g_wt16_i;  break;
            case 2: dst = g_wt16_r;  break;
            case 3: dst = g_wt16_l;  break;
            default: dst = g_wt16_r2; break;
        }
        for (int i = threadIdx.y; i < 32; i += 8)
            dst[(yo0 + i) * DIM + xo] = __float2half_rn(t[threadIdx.x][i]);
    }
}

// ---------------------------------------------------------------------------
// hist + weighted degree (by target)
// ---------------------------------------------------------------------------
__global__ void hist_deg_kernel(const int* __restrict__ ei, const float* __restrict__ ew)
{
    int i = blockIdx.x * blockDim.x + threadIdx.x;
    int stride = gridDim.x * blockDim.x;
    for (; i < E_EDGES; i += stride) {
        int c = ei[E_EDGES + i];
        atomicAdd(&g_hist[c], 1);
        atomicAdd(&g_deg[c], ew[i]);
    }
}

// ---------------------------------------------------------------------------
// 3-phase parallel exclusive scan
// ---------------------------------------------------------------------------
__global__ __launch_bounds__(1024) void scan1_kernel()
{
    __shared__ int wsum[32];
    int t = threadIdx.x;
    int idx = blockIdx.x * 1024 + t;
    int v = (idx < N_NODES) ? g_hist[idx] : 0;

    int incl = v;
    #pragma unroll
    for (int off = 1; off < 32; off <<= 1) {
        int n = __shfl_up_sync(0xffffffffu, incl, off);
        if ((t & 31) >= off) incl += n;
    }
    if ((t & 31) == 31) wsum[t >> 5] = incl;
    __syncthreads();
    if (t < 32) {
        int s = wsum[t];
        #pragma unroll
        for (int off = 1; off < 32; off <<= 1) {
            int n = __shfl_up_sync(0xffffffffu, s, off);
            if (t >= off) s += n;
        }
        wsum[t] = s - wsum[t];
    }
    __syncthreads();
    int excl = incl - v + wsum[t >> 5];
    if (idx < N_NODES) g_rowptr[idx] = excl;
    if (t == 1023) g_bsum[blockIdx.x] = excl + v;
}

__global__ void scan2_kernel()
{
    __shared__ int s[128];
    int t = threadIdx.x;
    s[t] = (t < SCAN_BLK) ? g_bsum[t] : 0;
    __syncthreads();
    #pragma unroll
    for (int off = 1; off < 128; off <<= 1) {
        int v = (t >= off) ? s[t - off] : 0;
        __syncthreads();
        s[t] += v;
        __syncthreads();
    }
    if (t < SCAN_BLK) g_bsum[t] = (t == 0) ? 0 : s[t - 1];
}

__global__ __launch_bounds__(1024) void scan3_kernel()
{
    int idx = blockIdx.x * 1024 + threadIdx.x;
    if (idx < N_NODES) {
        int v = g_rowptr[idx] + g_bsum[blockIdx.x];
        g_rowptr[idx] = v;
        g_wptr[idx]   = v;
    }
    if (idx == 0) g_rowptr[N_NODES] = E_EDGES;
}

// ---------------------------------------------------------------------------
// scatter edges into CSR slots; precompute gcn-norm per edge
// ---------------------------------------------------------------------------
__global__ void permute_kernel(const int* __restrict__ ei, const float* __restrict__ ew)
{
    int i = blockIdx.x * blockDim.x + threadIdx.x;
    int stride = gridDim.x * blockDim.x;
    for (; i < E_EDGES; i += stride) {
        int r = ei[i];
        int c = ei[E_EDGES + i];
        float w = ew[i];
        float dr = g_deg[r], dc = g_deg[c];
        float norm = (dr > 0.f && dc > 0.f)
                   ? rsqrtf(fmaxf(dr, 1e-12f)) * w * rsqrtf(fmaxf(dc, 1e-12f)) : 0.f;
        int pos = atomicAdd(&g_wptr[c], 1);
        g_srow[pos] = r;
        g_snw[pos]  = make_float2(norm, w);
    }
}

// ---------------------------------------------------------------------------
// gather: warp per target node; h fp16 in, agg/msg fp16 out; fp32 accumulation
// ---------------------------------------------------------------------------
__global__ __launch_bounds__(256) void gather_kernel()
{
    int node = (blockIdx.x * blockDim.x + threadIdx.x) >> 5;
    if (node >= N_NODES) return;
    const int lane = threadIdx.x & 31;
    const int beg = g_rowptr[node];
    const int end = g_rowptr[node + 1];

    float4 a = make_float4(0.f, 0.f, 0.f, 0.f);
    float4 m = make_float4(0.f, 0.f, 0.f, 0.f);
    const uint2* H = (const uint2*)g_h16;   // 4 halves per uint2

    for (int e = beg; e < end; ++e) {
        int r0 = g_srow[e];
        float2 nw = g_snw[e];
        uint2 u = H[r0 * 32 + lane];
        float2 f0 = __half22float2(*(__half2*)&u.x);
        float2 f1 = __half22float2(*(__half2*)&u.y);
        a.x += nw.x * f0.x; a.y += nw.x * f0.y; a.z += nw.x * f1.x; a.w += nw.x * f1.y;
        m.x += nw.y * f0.x; m.y += nw.y * f0.y; m.z += nw.y * f1.x; m.w += nw.y * f1.y;
    }

    float rc = 1.f / fmaxf((float)(end - beg), 1.f);
    __half2 a0 = __floats2half2_rn(a.x, a.y), a1 = __floats2half2_rn(a.z, a.w);
    __half2 m0 = __floats2half2_rn(m.x * rc, m.y * rc), m1 = __floats2half2_rn(m.z * rc, m.w * rc);
    uint2 ua = make_uint2(*(unsigned int*)&a0, *(unsigned int*)&a1);
    uint2 um = make_uint2(*(unsigned int*)&m0, *(unsigned int*)&m1);
    ((uint2*)g_agg16)[node * 32 + lane] = ua;
    ((uint2*)g_msg16)[node * 32 + lane] = um;
}

// ---------------------------------------------------------------------------
// gemm_pre: cp.async double-buffered tf32 mma.sync GEMM (proven path).
// out = fp16(x @ W_pre + b), stride 128.
// ---------------------------------------------------------------------------
__global__ __launch_bounds__(256, 2) void gemm_pre(
    const float* __restrict__ A1, const float* __restrict__ WT1,
    const float* __restrict__ bias, __half* __restrict__ out)
{
    extern __shared__ float smem[];
    const int CHF = 128 * 36;
    float* As = smem;
    float* Ws = smem + 2 * CHF;

    const int tid  = threadIdx.x;
    const int row0 = blockIdx.x * 128;
    const int wid  = tid >> 5;
    const int lane = tid & 31;
    const int gid  = lane >> 2;
    const int tig  = lane & 3;
    const int warpM = (wid >> 1) * 32;
    const int warpN = (wid & 1) * 64;

    int sr[4], sj[4], sgr[4];
    #pragma unroll
    for (int it = 0; it < 4; ++it) {
        int idx = tid + it * 256;
        sr[it] = idx >> 3;
        sj[it] = idx & 7;
        int gr = row0 + sr[it];
        sgr[it] = gr < N_NODES ? gr : N_NODES - 1;
    }

    auto stage = [&](int c, int buf) {
        const int kf = (c & 3) * 32;
        #pragma unroll
        for (int it = 0; it < 4; ++it)
            cp16(&As[buf * CHF + sr[it] * 36 + sj[it] * 4],
                 &A1[sgr[it] * DIM + kf + sj[it] * 4]);
        #pragma unroll
        for (int it = 0; it < 4; ++it)
            cp16(&Ws[buf * CHF + sr[it] * 36 + sj[it] * 4],
                 &WT1[sr[it] * DIM + kf + sj[it] * 4]);
        asm volatile("cp.async.commit_group;");
    };

    float acc[2][8][4];
    #pragma unroll
    for (int mt = 0; mt < 2; ++mt)
        #pragma unroll
        for (int nt = 0; nt < 8; ++nt)
            acc[mt][nt][0] = acc[mt][nt][1] = acc[mt][nt][2] = acc[mt][nt][3] = 0.f;

    stage(0, 0);

    for (int c = 0; c < 4; ++c) {
        if (c + 1 < 4) {
            stage(c + 1, (c + 1) & 1);
            asm volatile("cp.async.wait_group 1;");
        } else {
            asm volatile("cp.async.wait_group 0;");
        }
        __syncthreads();

        const float* Ab = &As[(c & 1) * CHF];
        const float* Wb = &Ws[(c & 1) * CHF];
        #pragma unroll
        for (int k8 = 0; k8 < 32; k8 += 8) {
            float a[2][4];
            #pragma unroll
            for (int mt = 0; mt < 2; ++mt) {
                int rb = warpM + mt * 16 + gid;
                a[mt][0] = to_tf32(Ab[rb * 36 + k8 + tig]);
                a[mt][1] = to_tf32(Ab[(rb + 8) * 36 + k8 + tig]);
                a[mt][2] = to_tf32(Ab[rb * 36 + k8 + tig + 4]);
                a[mt][3] = to_tf32(Ab[(rb + 8) * 36 + k8 + tig + 4]);
            }
            #pragma unroll
            for (int nt = 0; nt < 8; ++nt) {
                int nb = warpN + nt * 8 + gid;
                float b0 = Wb[nb * 36 + k8 + tig];
                float b1 = Wb[nb * 36 + k8 + tig + 4];
                mma_tf32(acc[0][nt], a[0][0], a[0][1], a[0][2], a[0][3], b0, b1);
                mma_tf32(acc[1][nt], a[1][0], a[1][1], a[1][2], a[1][3], b0, b1);
            }
        }
        __syncthreads();
    }

    #pragma unroll
    for (int mt = 0; mt < 2; ++mt) {
        #pragma unroll
        for (int nt = 0; nt < 8; ++nt) {
            int col = warpN + nt * 8 + 2 * tig;
            float2 bb = *(const float2*)&bias[col];
            #pragma unroll
            for (int half = 0; half < 2; ++half) {
                int gr = row0 + warpM + mt * 16 + gid + half * 8;
                if (gr >= N_NODES) continue;
                __half2 o = __floats2half2_rn(acc[mt][nt][half * 2 + 0] + bb.x,
                                              acc[mt][nt][half * 2 + 1] + bb.y);
                *(__half2*)&out[gr * 128 + col] = o;
            }
        }
    }
}

// ---------------------------------------------------------------------------
// fp16 dual GEMM with LDSM fragments:
//   C[M][128] = [A1 | A2] @ [WT1 ; WT2]^T + b, K=256, all fp16 operands.
// 256 thr, 8 warps 4Mx2N, warp tile 32x64, K chunks of 64 (128B SW128 rows).
// cp.async double-buffered. smem 64KB.
//  MODE 0 (ARMA): relu epi, out cols [0,128)
//  MODE 1 (SAGE): elu(leaky) epi, out cols [128,256)
// ---------------------------------------------------------------------------
template <int MODE>
__global__ __launch_bounds__(256, 2) void gemm_dual_f16(
    const __half* __restrict__ A1, const __half* __restrict__ WT1,
    const __half* __restrict__ A2, const __half* __restrict__ WT2,
    const float* __restrict__ bias, float* __restrict__ out)
{
    extern __shared__ char smemc[];
    const unsigned int smem_base = smem_u32(smemc);
    const int CHB = 16384;              // one 128x64 fp16 chunk, bytes
    const int B_OFF = 2 * CHB;          // Ws after As[2]

    const int tid  = threadIdx.x;
    const int row0 = blockIdx.x * 128;
    const int wid  = tid >> 5;
    const int lane = tid & 31;
    const int gid  = lane >> 2;
    const int tig  = lane & 3;
    const int warpM = (wid >> 1) * 32;
    const int warpN = (wid & 1) * 64;

    // staging: 1024 16B units per operand per chunk; 4 A + 4 B per thread
    int sr[4], sj[4], sgr[4];
    #pragma unroll
    for (int it = 0; it < 4; ++it) {
        int u = tid + it * 256;
        sr[it] = u >> 3;                 // row 0..127
        sj[it] = u & 7;                  // 16B unit within 128B row
        int gr = row0 + sr[it];
        sgr[it] = gr < N_NODES ? gr : N_NODES - 1;
    }

    auto stage = [&](int c, int buf) {
        const __half* srcA = (c >= 2) ? A2 : A1;
        const __half* srcW = (c >= 2) ? WT2 : WT1;
        const int kf = (c & 1) * 64;     // halves offset within 128-wide row
        char* Abuf = smemc + buf * CHB;
        char* Bbuf = smemc + B_OFF + buf * CHB;
        #pragma unroll
        for (int it = 0; it < 4; ++it) {
            unsigned int off = SMEM_SWIZZLE_128B((unsigned int)(sr[it] * 128 + sj[it] * 16));
            cp16(Abuf + off, &srcA[sgr[it] * DIM + kf + sj[it] * 8]);
            cp16(Bbuf + off, &srcW[sr[it]  * DIM + kf + sj[it] * 8]);
        }
        asm volatile("cp.async.commit_group;");
    };

    float acc[2][8][4];
    #pragma unroll
    for (int mt = 0; mt < 2; ++mt)
        #pragma unroll
        for (int nt = 0; nt < 8; ++nt)
            acc[mt][nt][0] = acc[mt][nt][1] = acc[mt][nt][2] = acc[mt][nt][3] = 0.f;

    stage(0, 0);

    const int tl = lane >> 3;            // ldmatrix tile index 0..3
    const int tr = lane & 7;             // row within tile

    for (int c = 0; c < 4; ++c) {
        if (c + 1 < 4) {
            stage(c + 1, (c + 1) & 1);
            asm volatile("cp.async.wait_group 1;");
        } else {
            asm volatile("cp.async.wait_group 0;");
        }
        __syncthreads();

        const unsigned int Ab = smem_base + (c & 1) * CHB;
        const unsigned int Bb = smem_base + B_OFF + (c & 1) * CHB;

        #pragma unroll
        for (int k16 = 0; k16 < 4; ++k16) {
            const int kb0 = k16 * 32;    // byte offset of this k16 step
            // A fragments: tiles t: row += (t&1)*8, kb += (t>>1)*16
            unsigned int a[2][4];
            #pragma unroll
            for (int mt = 0; mt < 2; ++mt) {
                int row = warpM + mt * 16 + (tl & 1) * 8 + tr;
                unsigned int off = SMEM_SWIZZLE_128B(
                    (unsigned int)(row * 128 + kb0 + (tl >> 1) * 16));
                ldsm_x4(a[mt][0], a[mt][1], a[mt][2], a[mt][3], Ab + off);
            }
            // B fragments: per np covers nt=2np,2np+1; tiles t: row += (t>>1)*8, kb += (t&1)*16
            #pragma unroll
            for (int np = 0; np < 4; ++np) {
                int row = warpN + np * 16 + (tl >> 1) * 8 + tr;
                unsigned int off = SMEM_SWIZZLE_128B(
                    (unsigned int)(row * 128 + kb0 + (tl & 1) * 16));
                unsigned int b0, b1, b2, b3;
                ldsm_x4(b0, b1, b2, b3, Bb + off);
                mma_f16(acc[0][2 * np],     a[0][0], a[0][1], a[0][2], a[0][3], b0, b1);
                mma_f16(acc[1][2 * np],     a[1][0], a[1][1], a[1][2], a[1][3], b0, b1);
                mma_f16(acc[0][2 * np + 1], a[0][0], a[0][1], a[0][2], a[0][3], b2, b3);
                mma_f16(acc[1][2 * np + 1], a[1][0], a[1][1], a[1][2], a[1][3], b2, b3);
            }
        }
        __syncthreads();
    }

    #pragma unroll
    for (int mt = 0; mt < 2; ++mt) {
        #pragma unroll
        for (int nt = 0; nt < 8; ++nt) {
            int col = warpN + nt * 8 + 2 * tig;
            float2 bb = *(const float2*)&bias[col];
            #pragma unroll
            for (int half = 0; half < 2; ++half) {
                int gr = row0 + warpM + mt * 16 + gid + half * 8;
                if (gr >= N_NODES) continue;
                float v0 = acc[mt][nt][half * 2 + 0] + bb.x;
                float v1 = acc[mt][nt][half * 2 + 1] + bb.y;
                float2 o;
                if (MODE == 0) {
                    o.x = fmaxf(v0, 0.f); o.y = fmaxf(v1, 0.f);
                    *(float2*)&out[gr * 256 + col] = o;
                } else {
                    o.x = v0 > 0.f ? v0 : expm1f(0.01f * v0);
                    o.y = v1 > 0.f ? v1 : expm1f(0.01f * v1);
                    *(float2*)&out[gr * 256 + 128 + col] = o;
                }
            }
        }
    }
}

// ---------------------------------------------------------------------------
extern "C" void kernel_launch(void* const* d_in, const int* in_sizes, int n_in,
                              void* d_out, int out_size)
{
    const float* x    = (const float*)d_in[0];
    const int*   ei   = (const int*)d_in[1];
    const float* ew   = (const float*)d_in[2];
    const float* Wpre = (const float*)d_in[3];
    const float* bpre = (const float*)d_in[4];
    const float* Wi   = (const float*)d_in[5];
    const float* Wr   = (const float*)d_in[6];
    const float* ba   = (const float*)d_in[7];
    const float* Wl   = (const float*)d_in[8];
    const float* bl   = (const float*)d_in[9];
    const float* Wr2  = (const float*)d_in[10];
    float* out = (float*)d_out;

    void *p_h16, *p_agg16, *p_msg16, *p_deg, *p_hist;
    void *p_wtpre, *p_wti, *p_wtr, *p_wtl, *p_wtr2;
    cudaGetSymbolAddress(&p_h16,   g_h16);
    cudaGetSymbolAddress(&p_agg16, g_agg16);
    cudaGetSymbolAddress(&p_msg16, g_msg16);
    cudaGetSymbolAddress(&p_deg,   g_deg);
    cudaGetSymbolAddress(&p_hist,  g_hist);
    cudaGetSymbolAddress(&p_wtpre, g_wt_pre);
    cudaGetSymbolAddress(&p_wti,   g_wt16_i);
    cudaGetSymbolAddress(&p_wtr,   g_wt16_r);
    cudaGetSymbolAddress(&p_wtl,   g_wt16_l);
    cudaGetSymbolAddress(&p_wtr2,  g_wt16_r2);

    const int SMEM_PRE = 4 * 128 * 36 * 4;   // 73,728 B
    const int SMEM_F16 = 4 * 16384;          // 65,536 B
    cudaFuncSetAttribute(gemm_pre, cudaFuncAttributeMaxDynamicSharedMemorySize, SMEM_PRE);
    cudaFuncSetAttribute(gemm_dual_f16<0>, cudaFuncAttributeMaxDynamicSharedMemorySize, SMEM_F16);
    cudaFuncSetAttribute(gemm_dual_f16<1>, cudaFuncAttributeMaxDynamicSharedMemorySize, SMEM_F16);

    cudaMemsetAsync(p_deg,  0, sizeof(float) * N_NODES);
    cudaMemsetAsync(p_hist, 0, sizeof(int)   * N_NODES);

    const int nblk = (N_NODES + 127) / 128;  // 782

    transpose_weights<<<dim3(4,4,5), dim3(32,8)>>>(Wpre, Wi, Wr, Wl, Wr2);
    hist_deg_kernel<<<1024, 256>>>(ei, ew);
    gemm_pre<<<nblk, 256, SMEM_PRE>>>(x, (const float*)p_wtpre, bpre, (__half*)p_h16);
    scan1_kernel<<<SCAN_BLK, 1024>>>();
    scan2_kernel<<<1, 128>>>();
    scan3_kernel<<<SCAN_BLK, 1024>>>();
    permute_kernel<<<1024, 256>>>(ei, ew);
    gather_kernel<<<(N_NODES * 32 + 255) / 256, 256>>>();
    gemm_dual_f16<0><<<nblk, 256, SMEM_F16>>>((const __half*)p_agg16, (const __half*)p_wti,
                                              (const __half*)p_h16,   (const __half*)p_wtr,
                                              ba, out);
    gemm_dual_f16<1><<<nblk, 256, SMEM_F16>>>((const __half*)p_msg16, (const __half*)p_wtl,
                                              (const __half*)p_h16,   (const __half*)p_wtr2,
                                              bl, out);
}

// round 15
// speedup vs baseline: 4.3717x; 1.0221x over previous
#include <cuda_runtime.h>
#include <cuda_fp16.h>
#include <stdint.h>
#include <math.h>

#define N_NODES 100000
#define E_EDGES 1600000
#define DIM 128
#define SCAN_BLK 98   // ceil(100000/1024)

// ---- scratch (device globals: allocation-free) ----
__device__ __half g_x16 [N_NODES * DIM];  // x, fp16
__device__ __half g_h16 [N_NODES * DIM];  // h, fp16
__device__ __half g_agg16[N_NODES * DIM]; // fp16
__device__ __half g_msg16[N_NODES * DIM]; // fp16, mean-scaled
__device__ float g_deg[N_NODES];
__device__ int   g_hist[N_NODES];
__device__ int   g_rowptr[N_NODES + 1];
__device__ int   g_wptr[N_NODES];
__device__ int   g_bsum[SCAN_BLK];
__device__ int   g_srow[E_EDGES];
__device__ float2 g_snw[E_EDGES];
// transposed fp16 weights [out][in]
__device__ __half g_wt16_pre[DIM * DIM];
__device__ __half g_wt16_i  [DIM * DIM];
__device__ __half g_wt16_r  [DIM * DIM];
__device__ __half g_wt16_l  [DIM * DIM];
__device__ __half g_wt16_r2 [DIM * DIM];

// ---------------------------------------------------------------------------
// helpers
// ---------------------------------------------------------------------------
__device__ __forceinline__ void mma_f16(float* c, unsigned int a0, unsigned int a1,
                                        unsigned int a2, unsigned int a3,
                                        unsigned int b0, unsigned int b1) {
    asm volatile(
        "mma.sync.aligned.m16n8k16.row.col.f32.f16.f16.f32 "
        "{%0,%1,%2,%3}, {%4,%5,%6,%7}, {%8,%9}, {%0,%1,%2,%3};"
        : "+f"(c[0]), "+f"(c[1]), "+f"(c[2]), "+f"(c[3])
        : "r"(a0), "r"(a1), "r"(a2), "r"(a3), "r"(b0), "r"(b1));
}

__device__ __forceinline__ void ldsm_x4(unsigned int& r0, unsigned int& r1,
                                        unsigned int& r2, unsigned int& r3,
                                        unsigned int addr) {
    asm volatile("ldmatrix.sync.aligned.m8n8.x4.shared.b16 {%0,%1,%2,%3}, [%4];"
                 : "=r"(r0), "=r"(r1), "=r"(r2), "=r"(r3) : "r"(addr));
}

__device__ __forceinline__ void cp16(void* dst_smem, const void* src) {
    unsigned int sa = (unsigned int)__cvta_generic_to_shared(dst_smem);
    asm volatile("cp.async.cg.shared.global [%0], [%1], 16;" :: "r"(sa), "l"(src));
}

__device__ __forceinline__ unsigned int smem_u32(const void* p) {
    unsigned int a;
    asm("{ .reg .u64 t; cvta.to.shared.u64 t, %1; cvt.u32.u64 %0, t; }"
        : "=r"(a) : "l"(p));
    return a;
}

#define SMEM_SWIZZLE_128B(byte_offset) \
    ((byte_offset) ^ (((byte_offset) >> 3) & 0x70))

// ---------------------------------------------------------------------------
// convert x -> fp16 (pure DRAM stream)
// ---------------------------------------------------------------------------
__global__ __launch_bounds__(256) void convert_x(const float4* __restrict__ x)
{
    uint2* o = (uint2*)g_x16;
    int i = blockIdx.x * blockDim.x + threadIdx.x;
    int stride = gridDim.x * blockDim.x;
    const int total = N_NODES * DIM / 4;
    for (; i < total; i += stride) {
        float4 v = x[i];
        __half2 h0 = __floats2half2_rn(v.x, v.y);
        __half2 h1 = __floats2half2_rn(v.z, v.w);
        o[i] = make_uint2(*(unsigned int*)&h0, *(unsigned int*)&h1);
    }
}

// ---------------------------------------------------------------------------
// transpose all 5 weights [in][out] -> [out][in], fp16
// ---------------------------------------------------------------------------
__global__ void transpose_weights(const float* __restrict__ W0, const float* __restrict__ W1,
                                  const float* __restrict__ W2, const float* __restrict__ W3,
                                  const float* __restrict__ W4)
{
    __shared__ float t[32][33];
    const float* src; __half* dst;
    switch (blockIdx.z) {
        case 0: src = W0; dst = g_wt16_pre; break;
        case 1: src = W1; dst = g_wt16_i;   break;
        case 2: src = W2; dst = g_wt16_r;   break;
        case 3: src = W3; dst = g_wt16_l;   break;
        default: src = W4; dst = g_wt16_r2; break;
    }
    int x = blockIdx.x * 32 + threadIdx.x;
    int y0 = blockIdx.y * 32;
    for (int i = threadIdx.y; i < 32; i += 8)
        t[i][threadIdx.x] = src[(y0 + i) * DIM + x];
    __syncthreads();
    int xo = blockIdx.y * 32 + threadIdx.x;
    int yo0 = blockIdx.x * 32;
    for (int i = threadIdx.y; i < 32; i += 8)
        dst[(yo0 + i) * DIM + xo] = __float2half_rn(t[threadIdx.x][i]);
}

// ---------------------------------------------------------------------------
// hist + weighted degree (by target)
// ---------------------------------------------------------------------------
__global__ void hist_deg_kernel(const int* __restrict__ ei, const float* __restrict__ ew)
{
    int i = blockIdx.x * blockDim.x + threadIdx.x;
    int stride = gridDim.x * blockDim.x;
    for (; i < E_EDGES; i += stride) {
        int c = ei[E_EDGES + i];
        atomicAdd(&g_hist[c], 1);
        atomicAdd(&g_deg[c], ew[i]);
    }
}

// ---------------------------------------------------------------------------
// 3-phase parallel exclusive scan
// ---------------------------------------------------------------------------
__global__ __launch_bounds__(1024) void scan1_kernel()
{
    __shared__ int wsum[32];
    int t = threadIdx.x;
    int idx = blockIdx.x * 1024 + t;
    int v = (idx < N_NODES) ? g_hist[idx] : 0;

    int incl = v;
    #pragma unroll
    for (int off = 1; off < 32; off <<= 1) {
        int n = __shfl_up_sync(0xffffffffu, incl, off);
        if ((t & 31) >= off) incl += n;
    }
    if ((t & 31) == 31) wsum[t >> 5] = incl;
    __syncthreads();
    if (t < 32) {
        int s = wsum[t];
        #pragma unroll
        for (int off = 1; off < 32; off <<= 1) {
            int n = __shfl_up_sync(0xffffffffu, s, off);
            if (t >= off) s += n;
        }
        wsum[t] = s - wsum[t];
    }
    __syncthreads();
    int excl = incl - v + wsum[t >> 5];
    if (idx < N_NODES) g_rowptr[idx] = excl;
    if (t == 1023) g_bsum[blockIdx.x] = excl + v;
}

__global__ void scan2_kernel()
{
    __shared__ int s[128];
    int t = threadIdx.x;
    s[t] = (t < SCAN_BLK) ? g_bsum[t] : 0;
    __syncthreads();
    #pragma unroll
    for (int off = 1; off < 128; off <<= 1) {
        int v = (t >= off) ? s[t - off] : 0;
        __syncthreads();
        s[t] += v;
        __syncthreads();
    }
    if (t < SCAN_BLK) g_bsum[t] = (t == 0) ? 0 : s[t - 1];
}

__global__ __launch_bounds__(1024) void scan3_kernel()
{
    int idx = blockIdx.x * 1024 + threadIdx.x;
    if (idx < N_NODES) {
        int v = g_rowptr[idx] + g_bsum[blockIdx.x];
        g_rowptr[idx] = v;
        g_wptr[idx]   = v;
    }
    if (idx == 0) g_rowptr[N_NODES] = E_EDGES;
}

// ---------------------------------------------------------------------------
// scatter edges into CSR slots; precompute gcn-norm per edge
// ---------------------------------------------------------------------------
__global__ void permute_kernel(const int* __restrict__ ei, const float* __restrict__ ew)
{
    int i = blockIdx.x * blockDim.x + threadIdx.x;
    int stride = gridDim.x * blockDim.x;
    for (; i < E_EDGES; i += stride) {
        int r = ei[i];
        int c = ei[E_EDGES + i];
        float w = ew[i];
        float dr = g_deg[r], dc = g_deg[c];
        float norm = (dr > 0.f && dc > 0.f)
                   ? rsqrtf(fmaxf(dr, 1e-12f)) * w * rsqrtf(fmaxf(dc, 1e-12f)) : 0.f;
        int pos = atomicAdd(&g_wptr[c], 1);
        g_srow[pos] = r;
        g_snw[pos]  = make_float2(norm, w);
    }
}

// ---------------------------------------------------------------------------
// gather: warp per target node; h fp16 in, agg/msg fp16 out; fp32 accumulation
// ---------------------------------------------------------------------------
__global__ __launch_bounds__(256) void gather_kernel()
{
    int node = (blockIdx.x * blockDim.x + threadIdx.x) >> 5;
    if (node >= N_NODES) return;
    const int lane = threadIdx.x & 31;
    const int beg = g_rowptr[node];
    const int end = g_rowptr[node + 1];

    float4 a = make_float4(0.f, 0.f, 0.f, 0.f);
    float4 m = make_float4(0.f, 0.f, 0.f, 0.f);
    const uint2* H = (const uint2*)g_h16;

    for (int e = beg; e < end; ++e) {
        int r0 = g_srow[e];
        float2 nw = g_snw[e];
        uint2 u = H[r0 * 32 + lane];
        float2 f0 = __half22float2(*(__half2*)&u.x);
        float2 f1 = __half22float2(*(__half2*)&u.y);
        a.x += nw.x * f0.x; a.y += nw.x * f0.y; a.z += nw.x * f1.x; a.w += nw.x * f1.y;
        m.x += nw.y * f0.x; m.y += nw.y * f0.y; m.z += nw.y * f1.x; m.w += nw.y * f1.y;
    }

    float rc = 1.f / fmaxf((float)(end - beg), 1.f);
    __half2 a0 = __floats2half2_rn(a.x, a.y), a1 = __floats2half2_rn(a.z, a.w);
    __half2 m0 = __floats2half2_rn(m.x * rc, m.y * rc), m1 = __floats2half2_rn(m.z * rc, m.w * rc);
    uint2 ua = make_uint2(*(unsigned int*)&a0, *(unsigned int*)&a1);
    uint2 um = make_uint2(*(unsigned int*)&m0, *(unsigned int*)&m1);
    ((uint2*)g_agg16)[node * 32 + lane] = ua;
    ((uint2*)g_msg16)[node * 32 + lane] = um;
}

// ---------------------------------------------------------------------------
// generic fp16 GEMM with LDSM fragments (proven layout from R13):
//   C[M][128] = A_cat[M][KTOT] @ W_cat + b
// 256 thr, 8 warps 4Mx2N, warp tile 32x64, K chunks of 64 (128B SW128 rows),
// cp.async double-buffered, smem 64KB, 2 CTAs/SM.
//  MODE 0 (KTOT=256): relu epi -> out fp32 cols [0,128) of 256-stride
//  MODE 1 (KTOT=256): elu(leaky) epi -> out fp32 cols [128,256)
//  MODE 2 (KTOT=128): h = A@W + b -> fp16, stride 128
// ---------------------------------------------------------------------------
template <int KTOT, int MODE>
__global__ __launch_bounds__(256, 2) void gemm_f16k(
    const __half* __restrict__ A1, const __half* __restrict__ WT1,
    const __half* __restrict__ A2, const __half* __restrict__ WT2,
    const float* __restrict__ bias, void* __restrict__ outv)
{
    extern __shared__ char smemc[];
    const unsigned int smem_base = smem_u32(smemc);
    const int CHB = 16384;              // one 128x64 fp16 chunk, bytes
    const int B_OFF = 2 * CHB;
    const int NC = KTOT / 64;

    const int tid  = threadIdx.x;
    const int row0 = blockIdx.x * 128;
    const int wid  = tid >> 5;
    const int lane = tid & 31;
    const int gid  = lane >> 2;
    const int tig  = lane & 3;
    const int warpM = (wid >> 1) * 32;
    const int warpN = (wid & 1) * 64;

    int sr[4], sj[4], sgr[4];
    #pragma unroll
    for (int it = 0; it < 4; ++it) {
        int u = tid + it * 256;
        sr[it] = u >> 3;
        sj[it] = u & 7;
        int gr = row0 + sr[it];
        sgr[it] = gr < N_NODES ? gr : N_NODES - 1;
    }

    auto stage = [&](int c, int buf) {
        const __half* srcA = (KTOT == 256 && c >= 2) ? A2 : A1;
        const __half* srcW = (KTOT == 256 && c >= 2) ? WT2 : WT1;
        const int kf = (c & 1) * 64;
        char* Abuf = smemc + buf * CHB;
        char* Bbuf = smemc + B_OFF + buf * CHB;
        #pragma unroll
        for (int it = 0; it < 4; ++it) {
            unsigned int off = SMEM_SWIZZLE_128B((unsigned int)(sr[it] * 128 + sj[it] * 16));
            cp16(Abuf + off, &srcA[sgr[it] * DIM + kf + sj[it] * 8]);
            cp16(Bbuf + off, &srcW[sr[it]  * DIM + kf + sj[it] * 8]);
        }
        asm volatile("cp.async.commit_group;");
    };

    float acc[2][8][4];
    #pragma unroll
    for (int mt = 0; mt < 2; ++mt)
        #pragma unroll
        for (int nt = 0; nt < 8; ++nt)
            acc[mt][nt][0] = acc[mt][nt][1] = acc[mt][nt][2] = acc[mt][nt][3] = 0.f;

    stage(0, 0);

    const int tl = lane >> 3;
    const int tr = lane & 7;

    for (int c = 0; c < NC; ++c) {
        if (c + 1 < NC) {
            stage(c + 1, (c + 1) & 1);
            asm volatile("cp.async.wait_group 1;");
        } else {
            asm volatile("cp.async.wait_group 0;");
        }
        __syncthreads();

        const unsigned int Ab = smem_base + (c & 1) * CHB;
        const unsigned int Bb = smem_base + B_OFF + (c & 1) * CHB;

        #pragma unroll
        for (int k16 = 0; k16 < 4; ++k16) {
            const int kb0 = k16 * 32;
            unsigned int a[2][4];
            #pragma unroll
            for (int mt = 0; mt < 2; ++mt) {
                int row = warpM + mt * 16 + (tl & 1) * 8 + tr;
                unsigned int off = SMEM_SWIZZLE_128B(
                    (unsigned int)(row * 128 + kb0 + (tl >> 1) * 16));
                ldsm_x4(a[mt][0], a[mt][1], a[mt][2], a[mt][3], Ab + off);
            }
            #pragma unroll
            for (int np = 0; np < 4; ++np) {
                int row = warpN + np * 16 + (tl >> 1) * 8 + tr;
                unsigned int off = SMEM_SWIZZLE_128B(
                    (unsigned int)(row * 128 + kb0 + (tl & 1) * 16));
                unsigned int b0, b1, b2, b3;
                ldsm_x4(b0, b1, b2, b3, Bb + off);
                mma_f16(acc[0][2 * np],     a[0][0], a[0][1], a[0][2], a[0][3], b0, b1);
                mma_f16(acc[1][2 * np],     a[1][0], a[1][1], a[1][2], a[1][3], b0, b1);
                mma_f16(acc[0][2 * np + 1], a[0][0], a[0][1], a[0][2], a[0][3], b2, b3);
                mma_f16(acc[1][2 * np + 1], a[1][0], a[1][1], a[1][2], a[1][3], b2, b3);
            }
        }
        __syncthreads();
    }

    #pragma unroll
    for (int mt = 0; mt < 2; ++mt) {
        #pragma unroll
        for (int nt = 0; nt < 8; ++nt) {
            int col = warpN + nt * 8 + 2 * tig;
            float2 bb = *(const float2*)&bias[col];
            #pragma unroll
            for (int half = 0; half < 2; ++half) {
                int gr = row0 + warpM + mt * 16 + gid + half * 8;
                if (gr >= N_NODES) continue;
                float v0 = acc[mt][nt][half * 2 + 0] + bb.x;
                float v1 = acc[mt][nt][half * 2 + 1] + bb.y;
                if (MODE == 0) {
                    float2 o = make_float2(fmaxf(v0, 0.f), fmaxf(v1, 0.f));
                    *(float2*)&((float*)outv)[gr * 256 + col] = o;
                } else if (MODE == 1) {
                    float2 o;
                    o.x = v0 > 0.f ? v0 : expm1f(0.01f * v0);
                    o.y = v1 > 0.f ? v1 : expm1f(0.01f * v1);
                    *(float2*)&((float*)outv)[gr * 256 + 128 + col] = o;
                } else {
                    __half2 o = __floats2half2_rn(v0, v1);
                    *(__half2*)&((__half*)outv)[gr * 128 + col] = o;
                }
            }
        }
    }
}

// ---------------------------------------------------------------------------
extern "C" void kernel_launch(void* const* d_in, const int* in_sizes, int n_in,
                              void* d_out, int out_size)
{
    const float* x    = (const float*)d_in[0];
    const int*   ei   = (const int*)d_in[1];
    const float* ew   = (const float*)d_in[2];
    const float* Wpre = (const float*)d_in[3];
    const float* bpre = (const float*)d_in[4];
    const float* Wi   = (const float*)d_in[5];
    const float* Wr   = (const float*)d_in[6];
    const float* ba   = (const float*)d_in[7];
    const float* Wl   = (const float*)d_in[8];
    const float* bl   = (const float*)d_in[9];
    const float* Wr2  = (const float*)d_in[10];
    float* out = (float*)d_out;

    void *p_x16, *p_h16, *p_agg16, *p_msg16, *p_deg, *p_hist;
    void *p_wtpre, *p_wti, *p_wtr, *p_wtl, *p_wtr2;
    cudaGetSymbolAddress(&p_x16,   g_x16);
    cudaGetSymbolAddress(&p_h16,   g_h16);
    cudaGetSymbolAddress(&p_agg16, g_agg16);
    cudaGetSymbolAddress(&p_msg16, g_msg16);
    cudaGetSymbolAddress(&p_deg,   g_deg);
    cudaGetSymbolAddress(&p_hist,  g_hist);
    cudaGetSymbolAddress(&p_wtpre, g_wt16_pre);
    cudaGetSymbolAddress(&p_wti,   g_wt16_i);
    cudaGetSymbolAddress(&p_wtr,   g_wt16_r);
    cudaGetSymbolAddress(&p_wtl,   g_wt16_l);
    cudaGetSymbolAddress(&p_wtr2,  g_wt16_r2);

    const int SMEM_F16 = 4 * 16384;          // 65,536 B
    cudaFuncSetAttribute(gemm_f16k<128,2>, cudaFuncAttributeMaxDynamicSharedMemorySize, SMEM_F16);
    cudaFuncSetAttribute(gemm_f16k<256,0>, cudaFuncAttributeMaxDynamicSharedMemorySize, SMEM_F16);
    cudaFuncSetAttribute(gemm_f16k<256,1>, cudaFuncAttributeMaxDynamicSharedMemorySize, SMEM_F16);

    cudaMemsetAsync(p_deg,  0, sizeof(float) * N_NODES);
    cudaMemsetAsync(p_hist, 0, sizeof(int)   * N_NODES);

    const int nblk = (N_NODES + 127) / 128;  // 782

    transpose_weights<<<dim3(4,4,5), dim3(32,8)>>>(Wpre, Wi, Wr, Wl, Wr2);
    convert_x<<<2048, 256>>>((const float4*)x);
    hist_deg_kernel<<<1024, 256>>>(ei, ew);
    gemm_f16k<128,2><<<nblk, 256, SMEM_F16>>>((const __half*)p_x16, (const __half*)p_wtpre,
                                              nullptr, nullptr, bpre, p_h16);
    scan1_kernel<<<SCAN_BLK, 1024>>>();
    scan2_kernel<<<1, 128>>>();
    scan3_kernel<<<SCAN_BLK, 1024>>>();
    permute_kernel<<<1024, 256>>>(ei, ew);
    gather_kernel<<<(N_NODES * 32 + 255) / 256, 256>>>();
    gemm_f16k<256,0><<<nblk, 256, SMEM_F16>>>((const __half*)p_agg16, (const __half*)p_wti,
                                              (const __half*)p_h16,   (const __half*)p_wtr,
                                              ba, out);
    gemm_f16k<256,1><<<nblk, 256, SMEM_F16>>>((const __half*)p_msg16, (const __half*)p_wtl,
                                              (const __half*)p_h16,   (const __half*)p_wtr2,
                                              bl, out);
}

// round 16
// speedup vs baseline: 4.6915x; 1.0732x over previous
#include <cuda_runtime.h>
#include <cuda_fp16.h>
#include <stdint.h>
#include <math.h>

#define N_NODES 100000
#define E_EDGES 1600000
#define DIM 128
#define SCAN_BLK 98   // ceil(100000/1024)

// ---- scratch (device globals: allocation-free) ----
__device__ __half g_x16 [N_NODES * DIM];
__device__ __half g_h16 [N_NODES * DIM];
__device__ __half g_agg16[N_NODES * DIM];
__device__ __half g_msg16[N_NODES * DIM];
__device__ float g_deg[N_NODES];
__device__ int   g_hist[N_NODES];
__device__ int   g_rowptr[N_NODES + 1];
__device__ int   g_wptr[N_NODES];
__device__ int   g_bsum[SCAN_BLK];
__device__ int   g_srow[E_EDGES];
__device__ __half2 g_snw16[E_EDGES];     // (norm, w) fp16
// transposed fp16 weights [out][in]
__device__ __half g_wt16_pre[DIM * DIM];
__device__ __half g_wt16_i  [DIM * DIM];
__device__ __half g_wt16_r  [DIM * DIM];
__device__ __half g_wt16_l  [DIM * DIM];
__device__ __half g_wt16_r2 [DIM * DIM];

// ---------------------------------------------------------------------------
// helpers
// ---------------------------------------------------------------------------
__device__ __forceinline__ void mma_f16(float* c, unsigned int a0, unsigned int a1,
                                        unsigned int a2, unsigned int a3,
                                        unsigned int b0, unsigned int b1) {
    asm volatile(
        "mma.sync.aligned.m16n8k16.row.col.f32.f16.f16.f32 "
        "{%0,%1,%2,%3}, {%4,%5,%6,%7}, {%8,%9}, {%0,%1,%2,%3};"
        : "+f"(c[0]), "+f"(c[1]), "+f"(c[2]), "+f"(c[3])
        : "r"(a0), "r"(a1), "r"(a2), "r"(a3), "r"(b0), "r"(b1));
}

__device__ __forceinline__ void ldsm_x4(unsigned int& r0, unsigned int& r1,
                                        unsigned int& r2, unsigned int& r3,
                                        unsigned int addr) {
    asm volatile("ldmatrix.sync.aligned.m8n8.x4.shared.b16 {%0,%1,%2,%3}, [%4];"
                 : "=r"(r0), "=r"(r1), "=r"(r2), "=r"(r3) : "r"(addr));
}

__device__ __forceinline__ void cp16(void* dst_smem, const void* src) {
    unsigned int sa = (unsigned int)__cvta_generic_to_shared(dst_smem);
    asm volatile("cp.async.cg.shared.global [%0], [%1], 16;" :: "r"(sa), "l"(src));
}

__device__ __forceinline__ unsigned int smem_u32(const void* p) {
    unsigned int a;
    asm("{ .reg .u64 t; cvta.to.shared.u64 t, %1; cvt.u32.u64 %0, t; }"
        : "=r"(a) : "l"(p));
    return a;
}

#define SMEM_SWIZZLE_128B(byte_offset) \
    ((byte_offset) ^ (((byte_offset) >> 3) & 0x70))

// ---------------------------------------------------------------------------
// prep: fused convert_x (blocks [0,1024)) + hist_deg (blocks [1024,2048))
//       + weight transpose (blocks [2048,2128))
// ---------------------------------------------------------------------------
__global__ __launch_bounds__(256) void prep_kernel(
    const float4* __restrict__ x, const int* __restrict__ ei,
    const float* __restrict__ ew,
    const float* __restrict__ W0, const float* __restrict__ W1,
    const float* __restrict__ W2, const float* __restrict__ W3,
    const float* __restrict__ W4)
{
    __shared__ float t[32][33];
    const int b = blockIdx.x;
    const int tid = threadIdx.x;

    if (b < 1024) {
        // convert x -> fp16
        uint2* o = (uint2*)g_x16;
        const int total = N_NODES * DIM / 4;
        for (int i = b * 256 + tid; i < total; i += 1024 * 256) {
            float4 v = x[i];
            __half2 h0 = __floats2half2_rn(v.x, v.y);
            __half2 h1 = __floats2half2_rn(v.z, v.w);
            o[i] = make_uint2(*(unsigned int*)&h0, *(unsigned int*)&h1);
        }
    } else if (b < 2048) {
        // hist + weighted degree
        for (int i = (b - 1024) * 256 + tid; i < E_EDGES; i += 1024 * 256) {
            int c = ei[E_EDGES + i];
            atomicAdd(&g_hist[c], 1);
            atomicAdd(&g_deg[c], ew[i]);
        }
    } else {
        // weight transpose: 16 tiles x 5 weights
        int b2 = b - 2048;
        int z = b2 >> 4;                 // weight index
        int tile = b2 & 15;
        int bx = tile & 3, by = tile >> 2;
        const float* src; __half* dst;
        switch (z) {
            case 0: src = W0; dst = g_wt16_pre; break;
            case 1: src = W1; dst = g_wt16_i;   break;
            case 2: src = W2; dst = g_wt16_r;   break;
            case 3: src = W3; dst = g_wt16_l;   break;
            default: src = W4; dst = g_wt16_r2; break;
        }
        int tx = tid & 31, ty = tid >> 5;
        int xc = bx * 32 + tx;
        int y0 = by * 32;
        for (int i = ty; i < 32; i += 8)
            t[i][tx] = src[(y0 + i) * DIM + xc];
        __syncthreads();
        int xo = by * 32 + tx;
        int yo0 = bx * 32;
        for (int i = ty; i < 32; i += 8)
            dst[(yo0 + i) * DIM + xo] = __float2half_rn(t[tx][i]);
    }
}

// ---------------------------------------------------------------------------
// 3-phase parallel exclusive scan
// ---------------------------------------------------------------------------
__global__ __launch_bounds__(1024) void scan1_kernel()
{
    __shared__ int wsum[32];
    int t = threadIdx.x;
    int idx = blockIdx.x * 1024 + t;
    int v = (idx < N_NODES) ? g_hist[idx] : 0;

    int incl = v;
    #pragma unroll
    for (int off = 1; off < 32; off <<= 1) {
        int n = __shfl_up_sync(0xffffffffu, incl, off);
        if ((t & 31) >= off) incl += n;
    }
    if ((t & 31) == 31) wsum[t >> 5] = incl;
    __syncthreads();
    if (t < 32) {
        int s = wsum[t];
        #pragma unroll
        for (int off = 1; off < 32; off <<= 1) {
            int n = __shfl_up_sync(0xffffffffu, s, off);
            if (t >= off) s += n;
        }
        wsum[t] = s - wsum[t];
    }
    __syncthreads();
    int excl = incl - v + wsum[t >> 5];
    if (idx < N_NODES) g_rowptr[idx] = excl;
    if (t == 1023) g_bsum[blockIdx.x] = excl + v;
}

__global__ void scan2_kernel()
{
    __shared__ int s[128];
    int t = threadIdx.x;
    s[t] = (t < SCAN_BLK) ? g_bsum[t] : 0;
    __syncthreads();
    #pragma unroll
    for (int off = 1; off < 128; off <<= 1) {
        int v = (t >= off) ? s[t - off] : 0;
        __syncthreads();
        s[t] += v;
        __syncthreads();
    }
    if (t < SCAN_BLK) g_bsum[t] = (t == 0) ? 0 : s[t - 1];
}

__global__ __launch_bounds__(1024) void scan3_kernel()
{
    int idx = blockIdx.x * 1024 + threadIdx.x;
    if (idx < N_NODES) {
        int v = g_rowptr[idx] + g_bsum[blockIdx.x];
        g_rowptr[idx] = v;
        g_wptr[idx]   = v;
    }
    if (idx == 0) g_rowptr[N_NODES] = E_EDGES;
}

// ---------------------------------------------------------------------------
// scatter edges into CSR slots; precompute gcn-norm; payload 8B/edge
// ---------------------------------------------------------------------------
__global__ void permute_kernel(const int* __restrict__ ei, const float* __restrict__ ew)
{
    int i = blockIdx.x * blockDim.x + threadIdx.x;
    int stride = gridDim.x * blockDim.x;
    for (; i < E_EDGES; i += stride) {
        int r = ei[i];
        int c = ei[E_EDGES + i];
        float w = ew[i];
        float dr = g_deg[r], dc = g_deg[c];
        float norm = (dr > 0.f && dc > 0.f)
                   ? rsqrtf(fmaxf(dr, 1e-12f)) * w * rsqrtf(fmaxf(dc, 1e-12f)) : 0.f;
        int pos = atomicAdd(&g_wptr[c], 1);
        g_srow[pos]  = r;
        g_snw16[pos] = __floats2half2_rn(norm, w);
    }
}

// ---------------------------------------------------------------------------
// gather: warp per target node; fp32 accumulation; fp16 in/out
// ---------------------------------------------------------------------------
__global__ __launch_bounds__(256) void gather_kernel()
{
    int node = (blockIdx.x * blockDim.x + threadIdx.x) >> 5;
    if (node >= N_NODES) return;
    const int lane = threadIdx.x & 31;
    const int beg = g_rowptr[node];
    const int end = g_rowptr[node + 1];

    float4 a = make_float4(0.f, 0.f, 0.f, 0.f);
    float4 m = make_float4(0.f, 0.f, 0.f, 0.f);
    const uint2* H = (const uint2*)g_h16;

    for (int e = beg; e < end; ++e) {
        int r0 = g_srow[e];
        __half2 nw = g_snw16[e];
        float nx = __low2float(nw), ny = __high2float(nw);
        uint2 u = H[r0 * 32 + lane];
        float2 f0 = __half22float2(*(__half2*)&u.x);
        float2 f1 = __half22float2(*(__half2*)&u.y);
        a.x += nx * f0.x; a.y += nx * f0.y; a.z += nx * f1.x; a.w += nx * f1.y;
        m.x += ny * f0.x; m.y += ny * f0.y; m.z += ny * f1.x; m.w += ny * f1.y;
    }

    float rc = 1.f / fmaxf((float)(end - beg), 1.f);
    __half2 a0 = __floats2half2_rn(a.x, a.y), a1 = __floats2half2_rn(a.z, a.w);
    __half2 m0 = __floats2half2_rn(m.x * rc, m.y * rc), m1 = __floats2half2_rn(m.z * rc, m.w * rc);
    uint2 ua = make_uint2(*(unsigned int*)&a0, *(unsigned int*)&a1);
    uint2 um = make_uint2(*(unsigned int*)&m0, *(unsigned int*)&m1);
    ((uint2*)g_agg16)[node * 32 + lane] = ua;
    ((uint2*)g_msg16)[node * 32 + lane] = um;
}

// ---------------------------------------------------------------------------
// fp16 LDSM GEMM core (proven R13 layout), shared by pre and dual kernels.
// Computes acc[2][8][4] for C-tile [row0:row0+128) x [0:128).
// ---------------------------------------------------------------------------
struct GemmArgs {
    const __half* A1; const __half* WT1;
    const __half* A2; const __half* WT2;
};

template <int KTOT>
__device__ __forceinline__ void gemm_core(
    char* smemc, unsigned int smem_base, int row0, const GemmArgs& g,
    float acc[2][8][4])
{
    const int CHB = 16384;
    const int B_OFF = 2 * CHB;
    const int NC = KTOT / 64;
    const int tid  = threadIdx.x;
    const int lane = tid & 31;
    const int wid  = tid >> 5;
    const int warpM = (wid >> 1) * 32;
    const int warpN = (wid & 1) * 64;

    int sr[4], sj[4], sgr[4];
    #pragma unroll
    for (int it = 0; it < 4; ++it) {
        int u = tid + it * 256;
        sr[it] = u >> 3;
        sj[it] = u & 7;
        int gr = row0 + sr[it];
        sgr[it] = gr < N_NODES ? gr : N_NODES - 1;
    }

    auto stage = [&](int c, int buf) {
        const __half* srcA = (KTOT == 256 && c >= 2) ? g.A2 : g.A1;
        const __half* srcW = (KTOT == 256 && c >= 2) ? g.WT2 : g.WT1;
        const int kf = (c & 1) * 64;
        char* Abuf = smemc + buf * CHB;
        char* Bbuf = smemc + B_OFF + buf * CHB;
        #pragma unroll
        for (int it = 0; it < 4; ++it) {
            unsigned int off = SMEM_SWIZZLE_128B((unsigned int)(sr[it] * 128 + sj[it] * 16));
            cp16(Abuf + off, &srcA[sgr[it] * DIM + kf + sj[it] * 8]);
            cp16(Bbuf + off, &srcW[sr[it]  * DIM + kf + sj[it] * 8]);
        }
        asm volatile("cp.async.commit_group;");
    };

    stage(0, 0);

    const int tl = lane >> 3;
    const int tr = lane & 7;

    for (int c = 0; c < NC; ++c) {
        if (c + 1 < NC) {
            stage(c + 1, (c + 1) & 1);
            asm volatile("cp.async.wait_group 1;");
        } else {
            asm volatile("cp.async.wait_group 0;");
        }
        __syncthreads();

        const unsigned int Ab = smem_base + (c & 1) * CHB;
        const unsigned int Bb = smem_base + B_OFF + (c & 1) * CHB;

        #pragma unroll
        for (int k16 = 0; k16 < 4; ++k16) {
            const int kb0 = k16 * 32;
            unsigned int a[2][4];
            #pragma unroll
            for (int mt = 0; mt < 2; ++mt) {
                int row = warpM + mt * 16 + (tl & 1) * 8 + tr;
                unsigned int off = SMEM_SWIZZLE_128B(
                    (unsigned int)(row * 128 + kb0 + (tl >> 1) * 16));
                ldsm_x4(a[mt][0], a[mt][1], a[mt][2], a[mt][3], Ab + off);
            }
            #pragma unroll
            for (int np = 0; np < 4; ++np) {
                int row = warpN + np * 16 + (tl >> 1) * 8 + tr;
                unsigned int off = SMEM_SWIZZLE_128B(
                    (unsigned int)(row * 128 + kb0 + (tl & 1) * 16));
                unsigned int b0, b1, b2, b3;
                ldsm_x4(b0, b1, b2, b3, Bb + off);
                mma_f16(acc[0][2 * np],     a[0][0], a[0][1], a[0][2], a[0][3], b0, b1);
                mma_f16(acc[1][2 * np],     a[1][0], a[1][1], a[1][2], a[1][3], b0, b1);
                mma_f16(acc[0][2 * np + 1], a[0][0], a[0][1], a[0][2], a[0][3], b2, b3);
                mma_f16(acc[1][2 * np + 1], a[1][0], a[1][1], a[1][2], a[1][3], b2, b3);
            }
        }
        __syncthreads();
    }
}

// ---------------------------------------------------------------------------
// gemm_pre: h = fp16(x16 @ Wpre^T + b), KTOT=128
// ---------------------------------------------------------------------------
__global__ __launch_bounds__(256, 2) void gemm_pre_f16(
    const float* __restrict__ bias)
{
    extern __shared__ char smemc[];
    const unsigned int smem_base = smem_u32(smemc);
    const int row0 = blockIdx.x * 128;
    const int tid = threadIdx.x;
    const int lane = tid & 31;
    const int wid  = tid >> 5;
    const int gid = lane >> 2, tig = lane & 3;
    const int warpM = (wid >> 1) * 32;
    const int warpN = (wid & 1) * 64;

    float acc[2][8][4];
    #pragma unroll
    for (int mt = 0; mt < 2; ++mt)
        #pragma unroll
        for (int nt = 0; nt < 8; ++nt)
            acc[mt][nt][0] = acc[mt][nt][1] = acc[mt][nt][2] = acc[mt][nt][3] = 0.f;

    GemmArgs g = { g_x16, g_wt16_pre, nullptr, nullptr };
    gemm_core<128>(smemc, smem_base, row0, g, acc);

    #pragma unroll
    for (int mt = 0; mt < 2; ++mt)
        #pragma unroll
        for (int nt = 0; nt < 8; ++nt) {
            int col = warpN + nt * 8 + 2 * tig;
            float2 bb = *(const float2*)&bias[col];
            #pragma unroll
            for (int half = 0; half < 2; ++half) {
                int gr = row0 + warpM + mt * 16 + gid + half * 8;
                if (gr >= N_NODES) continue;
                __half2 o = __floats2half2_rn(acc[mt][nt][half * 2 + 0] + bb.x,
                                              acc[mt][nt][half * 2 + 1] + bb.y);
                *(__half2*)&g_h16[gr * 128 + col] = o;
            }
        }
}

// ---------------------------------------------------------------------------
// both dual GEMMs in one launch: blockIdx.y = 0 (ARMA) / 1 (SAGE)
// ---------------------------------------------------------------------------
__global__ __launch_bounds__(256, 2) void gemm_dual_both(
    const float* __restrict__ ba, const float* __restrict__ bl,
    float* __restrict__ out)
{
    extern __shared__ char smemc[];
    const unsigned int smem_base = smem_u32(smemc);
    const int row0 = blockIdx.x * 128;
    const int mode = blockIdx.y;
    const int tid = threadIdx.x;
    const int lane = tid & 31;
    const int wid  = tid >> 5;
    const int gid = lane >> 2, tig = lane & 3;
    const int warpM = (wid >> 1) * 32;
    const int warpN = (wid & 1) * 64;

    float acc[2][8][4];
    #pragma unroll
    for (int mt = 0; mt < 2; ++mt)
        #pragma unroll
        for (int nt = 0; nt < 8; ++nt)
            acc[mt][nt][0] = acc[mt][nt][1] = acc[mt][nt][2] = acc[mt][nt][3] = 0.f;

    GemmArgs g;
    if (mode == 0) { g.A1 = g_agg16; g.WT1 = g_wt16_i; g.A2 = g_h16; g.WT2 = g_wt16_r; }
    else           { g.A1 = g_msg16; g.WT1 = g_wt16_l; g.A2 = g_h16; g.WT2 = g_wt16_r2; }
    gemm_core<256>(smemc, smem_base, row0, g, acc);

    const float* bias = (mode == 0) ? ba : bl;
    #pragma unroll
    for (int mt = 0; mt < 2; ++mt)
        #pragma unroll
        for (int nt = 0; nt < 8; ++nt) {
            int col = warpN + nt * 8 + 2 * tig;
            float2 bb = *(const float2*)&bias[col];
            #pragma unroll
            for (int half = 0; half < 2; ++half) {
                int gr = row0 + warpM + mt * 16 + gid + half * 8;
                if (gr >= N_NODES) continue;
                float v0 = acc[mt][nt][half * 2 + 0] + bb.x;
                float v1 = acc[mt][nt][half * 2 + 1] + bb.y;
                float2 o;
                if (mode == 0) {
                    o = make_float2(fmaxf(v0, 0.f), fmaxf(v1, 0.f));
                    *(float2*)&out[gr * 256 + col] = o;
                } else {
                    o.x = v0 > 0.f ? v0 : expm1f(0.01f * v0);
                    o.y = v1 > 0.f ? v1 : expm1f(0.01f * v1);
                    *(float2*)&out[gr * 256 + 128 + col] = o;
                }
            }
        }
}

// ---------------------------------------------------------------------------
extern "C" void kernel_launch(void* const* d_in, const int* in_sizes, int n_in,
                              void* d_out, int out_size)
{
    const float* x    = (const float*)d_in[0];
    const int*   ei   = (const int*)d_in[1];
    const float* ew   = (const float*)d_in[2];
    const float* Wpre = (const float*)d_in[3];
    const float* bpre = (const float*)d_in[4];
    const float* Wi   = (const float*)d_in[5];
    const float* Wr   = (const float*)d_in[6];
    const float* ba   = (const float*)d_in[7];
    const float* Wl   = (const float*)d_in[8];
    const float* bl   = (const float*)d_in[9];
    const float* Wr2  = (const float*)d_in[10];
    float* out = (float*)d_out;

    void *p_deg, *p_hist;
    cudaGetSymbolAddress(&p_deg,  g_deg);
    cudaGetSymbolAddress(&p_hist, g_hist);

    const int SMEM_F16 = 4 * 16384;          // 65,536 B
    cudaFuncSetAttribute(gemm_pre_f16,  cudaFuncAttributeMaxDynamicSharedMemorySize, SMEM_F16);
    cudaFuncSetAttribute(gemm_dual_both, cudaFuncAttributeMaxDynamicSharedMemorySize, SMEM_F16);

    cudaMemsetAsync(p_deg,  0, sizeof(float) * N_NODES);
    cudaMemsetAsync(p_hist, 0, sizeof(int)   * N_NODES);

    const int nblk = (N_NODES + 127) / 128;  // 782

    prep_kernel<<<2128, 256>>>((const float4*)x, ei, ew, Wpre, Wi, Wr, Wl, Wr2);
    scan1_kernel<<<SCAN_BLK, 1024>>>();
    scan2_kernel<<<1, 128>>>();
    scan3_kernel<<<SCAN_BLK, 1024>>>();
    gemm_pre_f16<<<nblk, 256, SMEM_F16>>>(bpre);
    permute_kernel<<<1024, 256>>>(ei, ew);
    gather_kernel<<<(N_NODES * 32 + 255) / 256, 256>>>();
    gemm_dual_both<<<dim3(nblk, 2), 256, SMEM_F16>>>(ba, bl, out);
}

// round 17
// speedup vs baseline: 4.7899x; 1.0210x over previous
#include <cuda_runtime.h>
#include <cuda_fp16.h>
#include <stdint.h>
#include <math.h>

#define N_NODES 100000
#define E_EDGES 1600000
#define DIM 128
#define SCAN_BLK 98   // ceil(100000/1024)

// ---- scratch (device globals: allocation-free, self-cleaning) ----
__device__ __half g_x16 [N_NODES * DIM];
__device__ __half g_h16 [N_NODES * DIM];
__device__ __half g_agg16[N_NODES * DIM];
__device__ __half g_msg16[N_NODES * DIM];
__device__ float g_deg[N_NODES];         // zeroed by gather each run
__device__ int   g_hist[N_NODES];        // zeroed by scan1 each run
__device__ int   g_rowptr[N_NODES + 1];
__device__ int   g_wptr[N_NODES];
__device__ int   g_bsum[SCAN_BLK];
__device__ int   g_srow[E_EDGES];
__device__ __half2 g_snw16[E_EDGES];     // (norm, w) fp16
// transposed fp16 weights [out][in]
__device__ __half g_wt16_pre[DIM * DIM];
__device__ __half g_wt16_i  [DIM * DIM];
__device__ __half g_wt16_r  [DIM * DIM];
__device__ __half g_wt16_l  [DIM * DIM];
__device__ __half g_wt16_r2 [DIM * DIM];

// ---------------------------------------------------------------------------
// helpers
// ---------------------------------------------------------------------------
__device__ __forceinline__ void mma_f16(float* c, unsigned int a0, unsigned int a1,
                                        unsigned int a2, unsigned int a3,
                                        unsigned int b0, unsigned int b1) {
    asm volatile(
        "mma.sync.aligned.m16n8k16.row.col.f32.f16.f16.f32 "
        "{%0,%1,%2,%3}, {%4,%5,%6,%7}, {%8,%9}, {%0,%1,%2,%3};"
        : "+f"(c[0]), "+f"(c[1]), "+f"(c[2]), "+f"(c[3])
        : "r"(a0), "r"(a1), "r"(a2), "r"(a3), "r"(b0), "r"(b1));
}

__device__ __forceinline__ void ldsm_x4(unsigned int& r0, unsigned int& r1,
                                        unsigned int& r2, unsigned int& r3,
                                        unsigned int addr) {
    asm volatile("ldmatrix.sync.aligned.m8n8.x4.shared.b16 {%0,%1,%2,%3}, [%4];"
                 : "=r"(r0), "=r"(r1), "=r"(r2), "=r"(r3) : "r"(addr));
}

__device__ __forceinline__ void cp16(void* dst_smem, const void* src) {
    unsigned int sa = (unsigned int)__cvta_generic_to_shared(dst_smem);
    asm volatile("cp.async.cg.shared.global [%0], [%1], 16;" :: "r"(sa), "l"(src));
}

__device__ __forceinline__ unsigned int smem_u32(const void* p) {
    unsigned int a;
    asm("{ .reg .u64 t; cvta.to.shared.u64 t, %1; cvt.u32.u64 %0, t; }"
        : "=r"(a) : "l"(p));
    return a;
}

#define SMEM_SWIZZLE_128B(byte_offset) \
    ((byte_offset) ^ (((byte_offset) >> 3) & 0x70))

// ---------------------------------------------------------------------------
// chain A head: convert_x (blocks [0,1024)) + weight transpose ([1024,1104))
// ---------------------------------------------------------------------------
__global__ __launch_bounds__(256) void prep_gemm_kernel(
    const float4* __restrict__ x,
    const float* __restrict__ W0, const float* __restrict__ W1,
    const float* __restrict__ W2, const float* __restrict__ W3,
    const float* __restrict__ W4)
{
    __shared__ float t[32][33];
    const int b = blockIdx.x;
    const int tid = threadIdx.x;

    if (b < 1024) {
        uint2* o = (uint2*)g_x16;
        const int total = N_NODES * DIM / 4;
        for (int i = b * 256 + tid; i < total; i += 1024 * 256) {
            float4 v = x[i];
            __half2 h0 = __floats2half2_rn(v.x, v.y);
            __half2 h1 = __floats2half2_rn(v.z, v.w);
            o[i] = make_uint2(*(unsigned int*)&h0, *(unsigned int*)&h1);
        }
    } else {
        int b2 = b - 1024;
        int z = b2 >> 4;
        int tile = b2 & 15;
        int bx = tile & 3, by = tile >> 2;
        const float* src; __half* dst;
        switch (z) {
            case 0: src = W0; dst = g_wt16_pre; break;
            case 1: src = W1; dst = g_wt16_i;   break;
            case 2: src = W2; dst = g_wt16_r;   break;
            case 3: src = W3; dst = g_wt16_l;   break;
            default: src = W4; dst = g_wt16_r2; break;
        }
        int tx = tid & 31, ty = tid >> 5;
        int xc = bx * 32 + tx;
        int y0 = by * 32;
        for (int i = ty; i < 32; i += 8)
            t[i][tx] = src[(y0 + i) * DIM + xc];
        __syncthreads();
        int xo = by * 32 + tx;
        int yo0 = bx * 32;
        for (int i = ty; i < 32; i += 8)
            dst[(yo0 + i) * DIM + xo] = __float2half_rn(t[tx][i]);
    }
}

// ---------------------------------------------------------------------------
// chain B head: hist + weighted degree (by target)
// ---------------------------------------------------------------------------
__global__ void hist_deg_kernel(const int* __restrict__ ei, const float* __restrict__ ew)
{
    int i = blockIdx.x * blockDim.x + threadIdx.x;
    int stride = gridDim.x * blockDim.x;
    for (; i < E_EDGES; i += stride) {
        int c = ei[E_EDGES + i];
        atomicAdd(&g_hist[c], 1);
        atomicAdd(&g_deg[c], ew[i]);
    }
}

// ---------------------------------------------------------------------------
// 3-phase parallel exclusive scan; scan1 self-cleans g_hist
// ---------------------------------------------------------------------------
__global__ __launch_bounds__(1024) void scan1_kernel()
{
    __shared__ int wsum[32];
    int t = threadIdx.x;
    int idx = blockIdx.x * 1024 + t;
    int v = 0;
    if (idx < N_NODES) {
        v = g_hist[idx];
        g_hist[idx] = 0;               // self-clean for next run
    }

    int incl = v;
    #pragma unroll
    for (int off = 1; off < 32; off <<= 1) {
        int n = __shfl_up_sync(0xffffffffu, incl, off);
        if ((t & 31) >= off) incl += n;
    }
    if ((t & 31) == 31) wsum[t >> 5] = incl;
    __syncthreads();
    if (t < 32) {
        int s = wsum[t];
        #pragma unroll
        for (int off = 1; off < 32; off <<= 1) {
            int n = __shfl_up_sync(0xffffffffu, s, off);
            if (t >= off) s += n;
        }
        wsum[t] = s - wsum[t];
    }
    __syncthreads();
    int excl = incl - v + wsum[t >> 5];
    if (idx < N_NODES) g_rowptr[idx] = excl;
    if (t == 1023) g_bsum[blockIdx.x] = excl + v;
}

__global__ void scan2_kernel()
{
    __shared__ int s[128];
    int t = threadIdx.x;
    s[t] = (t < SCAN_BLK) ? g_bsum[t] : 0;
    __syncthreads();
    #pragma unroll
    for (int off = 1; off < 128; off <<= 1) {
        int v = (t >= off) ? s[t - off] : 0;
        __syncthreads();
        s[t] += v;
        __syncthreads();
    }
    if (t < SCAN_BLK) g_bsum[t] = (t == 0) ? 0 : s[t - 1];
}

__global__ __launch_bounds__(1024) void scan3_kernel()
{
    int idx = blockIdx.x * 1024 + threadIdx.x;
    if (idx < N_NODES) {
        int v = g_rowptr[idx] + g_bsum[blockIdx.x];
        g_rowptr[idx] = v;
        g_wptr[idx]   = v;
    }
    if (idx == 0) g_rowptr[N_NODES] = E_EDGES;
}

// ---------------------------------------------------------------------------
// scatter edges into CSR slots; precompute gcn-norm; payload 8B/edge
// ---------------------------------------------------------------------------
__global__ void permute_kernel(const int* __restrict__ ei, const float* __restrict__ ew)
{
    int i = blockIdx.x * blockDim.x + threadIdx.x;
    int stride = gridDim.x * blockDim.x;
    for (; i < E_EDGES; i += stride) {
        int r = ei[i];
        int c = ei[E_EDGES + i];
        float w = ew[i];
        float dr = g_deg[r], dc = g_deg[c];
        float norm = (dr > 0.f && dc > 0.f)
                   ? rsqrtf(fmaxf(dr, 1e-12f)) * w * rsqrtf(fmaxf(dc, 1e-12f)) : 0.f;
        int pos = atomicAdd(&g_wptr[c], 1);
        g_srow[pos]  = r;
        g_snw16[pos] = __floats2half2_rn(norm, w);
    }
}

// ---------------------------------------------------------------------------
// gather: warp per target node; fp32 accumulation; self-cleans g_deg
// ---------------------------------------------------------------------------
__global__ __launch_bounds__(256) void gather_kernel()
{
    int node = (blockIdx.x * blockDim.x + threadIdx.x) >> 5;
    if (node >= N_NODES) return;
    const int lane = threadIdx.x & 31;
    const int beg = g_rowptr[node];
    const int end = g_rowptr[node + 1];

    if (lane == 0) g_deg[node] = 0.f;   // self-clean (permute was last reader)

    float4 a = make_float4(0.f, 0.f, 0.f, 0.f);
    float4 m = make_float4(0.f, 0.f, 0.f, 0.f);
    const uint2* H = (const uint2*)g_h16;

    for (int e = beg; e < end; ++e) {
        int r0 = g_srow[e];
        __half2 nw = g_snw16[e];
        float nx = __low2float(nw), ny = __high2float(nw);
        uint2 u = H[r0 * 32 + lane];
        float2 f0 = __half22float2(*(__half2*)&u.x);
        float2 f1 = __half22float2(*(__half2*)&u.y);
        a.x += nx * f0.x; a.y += nx * f0.y; a.z += nx * f1.x; a.w += nx * f1.y;
        m.x += ny * f0.x; m.y += ny * f0.y; m.z += ny * f1.x; m.w += ny * f1.y;
    }

    float rc = 1.f / fmaxf((float)(end - beg), 1.f);
    __half2 a0 = __floats2half2_rn(a.x, a.y), a1 = __floats2half2_rn(a.z, a.w);
    __half2 m0 = __floats2half2_rn(m.x * rc, m.y * rc), m1 = __floats2half2_rn(m.z * rc, m.w * rc);
    uint2 ua = make_uint2(*(unsigned int*)&a0, *(unsigned int*)&a1);
    uint2 um = make_uint2(*(unsigned int*)&m0, *(unsigned int*)&m1);
    ((uint2*)g_agg16)[node * 32 + lane] = ua;
    ((uint2*)g_msg16)[node * 32 + lane] = um;
}

// ---------------------------------------------------------------------------
// fp16 LDSM GEMM core (proven R13 layout)
// ---------------------------------------------------------------------------
struct GemmArgs {
    const __half* A1; const __half* WT1;
    const __half* A2; const __half* WT2;
};

template <int KTOT>
__device__ __forceinline__ void gemm_core(
    char* smemc, unsigned int smem_base, int row0, const GemmArgs& g,
    float acc[2][8][4])
{
    const int CHB = 16384;
    const int B_OFF = 2 * CHB;
    const int NC = KTOT / 64;
    const int tid  = threadIdx.x;
    const int lane = tid & 31;
    const int wid  = tid >> 5;
    const int warpM = (wid >> 1) * 32;
    const int warpN = (wid & 1) * 64;

    int sr[4], sj[4], sgr[4];
    #pragma unroll
    for (int it = 0; it < 4; ++it) {
        int u = tid + it * 256;
        sr[it] = u >> 3;
        sj[it] = u & 7;
        int gr = row0 + sr[it];
        sgr[it] = gr < N_NODES ? gr : N_NODES - 1;
    }

    auto stage = [&](int c, int buf) {
        const __half* srcA = (KTOT == 256 && c >= 2) ? g.A2 : g.A1;
        const __half* srcW = (KTOT == 256 && c >= 2) ? g.WT2 : g.WT1;
        const int kf = (c & 1) * 64;
        char* Abuf = smemc + buf * CHB;
        char* Bbuf = smemc + B_OFF + buf * CHB;
        #pragma unroll
        for (int it = 0; it < 4; ++it) {
            unsigned int off = SMEM_SWIZZLE_128B((unsigned int)(sr[it] * 128 + sj[it] * 16));
            cp16(Abuf + off, &srcA[sgr[it] * DIM + kf + sj[it] * 8]);
            cp16(Bbuf + off, &srcW[sr[it]  * DIM + kf + sj[it] * 8]);
        }
        asm volatile("cp.async.commit_group;");
    };

    stage(0, 0);

    const int tl = lane >> 3;
    const int tr = lane & 7;

    for (int c = 0; c < NC; ++c) {
        if (c + 1 < NC) {
            stage(c + 1, (c + 1) & 1);
            asm volatile("cp.async.wait_group 1;");
        } else {
            asm volatile("cp.async.wait_group 0;");
        }
        __syncthreads();

        const unsigned int Ab = smem_base + (c & 1) * CHB;
        const unsigned int Bb = smem_base + B_OFF + (c & 1) * CHB;

        #pragma unroll
        for (int k16 = 0; k16 < 4; ++k16) {
            const int kb0 = k16 * 32;
            unsigned int a[2][4];
            #pragma unroll
            for (int mt = 0; mt < 2; ++mt) {
                int row = warpM + mt * 16 + (tl & 1) * 8 + tr;
                unsigned int off = SMEM_SWIZZLE_128B(
                    (unsigned int)(row * 128 + kb0 + (tl >> 1) * 16));
                ldsm_x4(a[mt][0], a[mt][1], a[mt][2], a[mt][3], Ab + off);
            }
            #pragma unroll
            for (int np = 0; np < 4; ++np) {
                int row = warpN + np * 16 + (tl >> 1) * 8 + tr;
                unsigned int off = SMEM_SWIZZLE_128B(
                    (unsigned int)(row * 128 + kb0 + (tl & 1) * 16));
                unsigned int b0, b1, b2, b3;
                ldsm_x4(b0, b1, b2, b3, Bb + off);
                mma_f16(acc[0][2 * np],     a[0][0], a[0][1], a[0][2], a[0][3], b0, b1);
                mma_f16(acc[1][2 * np],     a[1][0], a[1][1], a[1][2], a[1][3], b0, b1);
                mma_f16(acc[0][2 * np + 1], a[0][0], a[0][1], a[0][2], a[0][3], b2, b3);
                mma_f16(acc[1][2 * np + 1], a[1][0], a[1][1], a[1][2], a[1][3], b2, b3);
            }
        }
        __syncthreads();
    }
}

// ---------------------------------------------------------------------------
// gemm_pre: h = fp16(x16 @ Wpre^T + b), KTOT=128
// ---------------------------------------------------------------------------
__global__ __launch_bounds__(256, 2) void gemm_pre_f16(
    const float* __restrict__ bias)
{
    extern __shared__ char smemc[];
    const unsigned int smem_base = smem_u32(smemc);
    const int row0 = blockIdx.x * 128;
    const int tid = threadIdx.x;
    const int lane = tid & 31;
    const int wid  = tid >> 5;
    const int gid = lane >> 2, tig = lane & 3;
    const int warpM = (wid >> 1) * 32;
    const int warpN = (wid & 1) * 64;

    float acc[2][8][4];
    #pragma unroll
    for (int mt = 0; mt < 2; ++mt)
        #pragma unroll
        for (int nt = 0; nt < 8; ++nt)
            acc[mt][nt][0] = acc[mt][nt][1] = acc[mt][nt][2] = acc[mt][nt][3] = 0.f;

    GemmArgs g = { g_x16, g_wt16_pre, nullptr, nullptr };
    gemm_core<128>(smemc, smem_base, row0, g, acc);

    #pragma unroll
    for (int mt = 0; mt < 2; ++mt)
        #pragma unroll
        for (int nt = 0; nt < 8; ++nt) {
            int col = warpN + nt * 8 + 2 * tig;
            float2 bb = *(const float2*)&bias[col];
            #pragma unroll
            for (int half = 0; half < 2; ++half) {
                int gr = row0 + warpM + mt * 16 + gid + half * 8;
                if (gr >= N_NODES) continue;
                __half2 o = __floats2half2_rn(acc[mt][nt][half * 2 + 0] + bb.x,
                                              acc[mt][nt][half * 2 + 1] + bb.y);
                *(__half2*)&g_h16[gr * 128 + col] = o;
            }
        }
}

// ---------------------------------------------------------------------------
// both dual GEMMs in one launch: blockIdx.y = 0 (ARMA) / 1 (SAGE)
// ---------------------------------------------------------------------------
__global__ __launch_bounds__(256, 2) void gemm_dual_both(
    const float* __restrict__ ba, const float* __restrict__ bl,
    float* __restrict__ out)
{
    extern __shared__ char smemc[];
    const unsigned int smem_base = smem_u32(smemc);
    const int row0 = blockIdx.x * 128;
    const int mode = blockIdx.y;
    const int tid = threadIdx.x;
    const int lane = tid & 31;
    const int wid  = tid >> 5;
    const int gid = lane >> 2, tig = lane & 3;
    const int warpM = (wid >> 1) * 32;
    const int warpN = (wid & 1) * 64;

    float acc[2][8][4];
    #pragma unroll
    for (int mt = 0; mt < 2; ++mt)
        #pragma unroll
        for (int nt = 0; nt < 8; ++nt)
            acc[mt][nt][0] = acc[mt][nt][1] = acc[mt][nt][2] = acc[mt][nt][3] = 0.f;

    GemmArgs g;
    if (mode == 0) { g.A1 = g_agg16; g.WT1 = g_wt16_i; g.A2 = g_h16; g.WT2 = g_wt16_r; }
    else           { g.A1 = g_msg16; g.WT1 = g_wt16_l; g.A2 = g_h16; g.WT2 = g_wt16_r2; }
    gemm_core<256>(smemc, smem_base, row0, g, acc);

    const float* bias = (mode == 0) ? ba : bl;
    #pragma unroll
    for (int mt = 0; mt < 2; ++mt)
        #pragma unroll
        for (int nt = 0; nt < 8; ++nt) {
            int col = warpN + nt * 8 + 2 * tig;
            float2 bb = *(const float2*)&bias[col];
            #pragma unroll
            for (int half = 0; half < 2; ++half) {
                int gr = row0 + warpM + mt * 16 + gid + half * 8;
                if (gr >= N_NODES) continue;
                float v0 = acc[mt][nt][half * 2 + 0] + bb.x;
                float v1 = acc[mt][nt][half * 2 + 1] + bb.y;
                float2 o;
                if (mode == 0) {
                    o = make_float2(fmaxf(v0, 0.f), fmaxf(v1, 0.f));
                    *(float2*)&out[gr * 256 + col] = o;
                } else {
                    o.x = v0 > 0.f ? v0 : expm1f(0.01f * v0);
                    o.y = v1 > 0.f ? v1 : expm1f(0.01f * v1);
                    *(float2*)&out[gr * 256 + 128 + col] = o;
                }
            }
        }
}

// ---------------------------------------------------------------------------
extern "C" void kernel_launch(void* const* d_in, const int* in_sizes, int n_in,
                              void* d_out, int out_size)
{
    const float* x    = (const float*)d_in[0];
    const int*   ei   = (const int*)d_in[1];
    const float* ew   = (const float*)d_in[2];
    const float* Wpre = (const float*)d_in[3];
    const float* bpre = (const float*)d_in[4];
    const float* Wi   = (const float*)d_in[5];
    const float* Wr   = (const float*)d_in[6];
    const float* ba   = (const float*)d_in[7];
    const float* Wl   = (const float*)d_in[8];
    const float* bl   = (const float*)d_in[9];
    const float* Wr2  = (const float*)d_in[10];
    float* out = (float*)d_out;

    const int SMEM_F16 = 4 * 16384;          // 65,536 B
    cudaFuncSetAttribute(gemm_pre_f16,  cudaFuncAttributeMaxDynamicSharedMemorySize, SMEM_F16);
    cudaFuncSetAttribute(gemm_dual_both, cudaFuncAttributeMaxDynamicSharedMemorySize, SMEM_F16);

    const int nblk = (N_NODES + 127) / 128;  // 782

    // fork/join: chain B (edge) on s2 runs concurrently with chain A (gemm) on 0
    cudaStream_t s2;
    cudaStreamCreate(&s2);
    cudaEvent_t evF, evJ;
    cudaEventCreateWithFlags(&evF, cudaEventDisableTiming);
    cudaEventCreateWithFlags(&evJ, cudaEventDisableTiming);

    cudaEventRecord(evF, 0);
    cudaStreamWaitEvent(s2, evF, 0);

    // chain B: edge preprocessing
    hist_deg_kernel<<<1024, 256, 0, s2>>>(ei, ew);
    scan1_kernel<<<SCAN_BLK, 1024, 0, s2>>>();
    scan2_kernel<<<1, 128, 0, s2>>>();
    scan3_kernel<<<SCAN_BLK, 1024, 0, s2>>>();
    permute_kernel<<<1024, 256, 0, s2>>>(ei, ew);
    cudaEventRecord(evJ, s2);

    // chain A: feature preprocessing + pre GEMM
    prep_gemm_kernel<<<1104, 256>>>((const float4*)x, Wpre, Wi, Wr, Wl, Wr2);
    gemm_pre_f16<<<nblk, 256, SMEM_F16>>>(bpre);

    // join, then gather + output GEMMs
    cudaStreamWaitEvent(0, evJ, 0);
    gather_kernel<<<(N_NODES * 32 + 255) / 256, 256>>>();
    gemm_dual_both<<<dim3(nblk, 2), 256, SMEM_F16>>>(ba, bl, out);

    cudaEventDestroy(evF);
    cudaEventDestroy(evJ);
    cudaStreamDestroy(s2);
}